// round 1
// baseline (speedup 1.0000x reference)
#include <cuda_runtime.h>
#include <math.h>

// ---------------- problem constants ----------------
#define NTOT 4096      // B*T
#define TLEN 128
#define BSZ  32
#define KST  16
#define LDIM 16
#define H1   400
#define DIN  784

// ---------------- scratch (device globals; no runtime alloc) ----------------
__device__ float g_h   [NTOT * H1];
__device__ float g_ml  [NTOT * 32];
__device__ float g_z   [NTOT * LDIM];
__device__ float g_base[NTOT * H1];
__device__ float g_logbk[NTOT * KST];          // [b][t][k]
__device__ float g_lA[KST * KST];
__device__ float g_lp[KST];
__device__ float g_alpha[BSZ * TLEN * KST];
__device__ float g_beta [BSZ * TLEN * KST];

// ---------------- small prep: lp, lA ----------------
__global__ void prep_lplA(const float* __restrict__ log_pi,
                          const float* __restrict__ log_A) {
    int t = threadIdx.x;
    if (t < 16) {
        float m = -1e30f;
        for (int j = 0; j < 16; j++) m = fmaxf(m, log_A[t * 16 + j]);
        float s = 0.f;
        for (int j = 0; j < 16; j++) s += expf(log_A[t * 16 + j] - m);
        for (int j = 0; j < 16; j++)
            g_lA[t * 16 + j] = logf(expf(log_A[t * 16 + j] - m) / s + 1e-9f);
    } else if (t == 16) {
        float m = -1e30f;
        for (int j = 0; j < 16; j++) m = fmaxf(m, log_pi[j]);
        float s = 0.f;
        for (int j = 0; j < 16; j++) s += expf(log_pi[j] - m);
        for (int j = 0; j < 16; j++)
            g_lp[j] = logf(expf(log_pi[j] - m) / s + 1e-9f);
    }
}

// ---------------- generic tiled GEMM: C = act(A @ B^T + bias) ----------------
// A: [M, K] lda, B: [N, K] ldb, C: [M, N] ldc.  M % 64 == 0, K % 16 == 0.
__global__ __launch_bounds__(256) void gemm64(
    const float* __restrict__ A, int lda,
    const float* __restrict__ B, int ldb,
    const float* __restrict__ bias,
    float* __restrict__ C, int ldc,
    int M, int N, int K, int relu_flag)
{
    __shared__ float As[16][68];
    __shared__ float Bs[16][68];
    int tid = threadIdx.x;
    int tx = tid & 15, ty = tid >> 4;
    int m0 = blockIdx.x * 64, j0 = blockIdx.y * 64;
    int lr = tid >> 2;          // 0..63
    int lc = (tid & 3) * 4;     // 0,4,8,12

    float c[4][4];
    #pragma unroll
    for (int r = 0; r < 4; r++)
        #pragma unroll
        for (int s = 0; s < 4; s++) c[r][s] = 0.f;

    for (int kt = 0; kt < K; kt += 16) {
        float4 av = *(const float4*)&A[(size_t)(m0 + lr) * lda + kt + lc];
        float4 bv = make_float4(0.f, 0.f, 0.f, 0.f);
        if (j0 + lr < N)
            bv = *(const float4*)&B[(size_t)(j0 + lr) * ldb + kt + lc];
        __syncthreads();
        As[lc + 0][lr] = av.x; As[lc + 1][lr] = av.y;
        As[lc + 2][lr] = av.z; As[lc + 3][lr] = av.w;
        Bs[lc + 0][lr] = bv.x; Bs[lc + 1][lr] = bv.y;
        Bs[lc + 2][lr] = bv.z; Bs[lc + 3][lr] = bv.w;
        __syncthreads();
        #pragma unroll
        for (int kk = 0; kk < 16; kk++) {
            float4 a4 = *(const float4*)&As[kk][ty * 4];
            float4 b4 = *(const float4*)&Bs[kk][tx * 4];
            float a_[4] = {a4.x, a4.y, a4.z, a4.w};
            float b_[4] = {b4.x, b4.y, b4.z, b4.w};
            #pragma unroll
            for (int r = 0; r < 4; r++)
                #pragma unroll
                for (int s = 0; s < 4; s++)
                    c[r][s] = fmaf(a_[r], b_[s], c[r][s]);
        }
    }
    #pragma unroll
    for (int r = 0; r < 4; r++) {
        int m = m0 + ty * 4 + r;
        #pragma unroll
        for (int s = 0; s < 4; s++) {
            int j = j0 + tx * 4 + s;
            if (j < N) {
                float v = c[r][s] + bias[j];
                if (relu_flag) v = fmaxf(v, 0.f);
                C[(size_t)m * ldc + j] = v;
            }
        }
    }
}

// ---------------- reparameterization ----------------
__global__ void reparam_kernel(const float* __restrict__ eps) {
    int idx = blockIdx.x * blockDim.x + threadIdx.x;
    if (idx < NTOT * LDIM) {
        int n = idx >> 4, l = idx & 15;
        g_z[idx] = g_ml[n * 32 + l] + eps[idx] * expf(0.5f * g_ml[n * 32 + 16 + l]);
    }
}

// ---------------- fused decoder GEMM + BCE reduction ----------------
// grid (64, 16): blockIdx.x = n-tile (64 rows), blockIdx.y = k (mixture state)
// Computes log_bk[n][k] = -(1/100) * sum_o bce(s, y) with
//   s = relu(base[n,:] + Wx[:,k]) @ dec_w[o,:] + dec_b[o]
#define ASH_PITCH 404
#define DEC_SMEM_FLOATS (64 * ASH_PITCH + 2 * 16 * 68 + 400)
#define DEC_SMEM_BYTES  (DEC_SMEM_FLOATS * 4)

__global__ __launch_bounds__(256, 2) void dec_bce(
    const float* __restrict__ dec_fc_w,
    const float* __restrict__ dec_w,
    const float* __restrict__ dec_b,
    const float* __restrict__ y)
{
    extern __shared__ float sm[];
    float* Ash = sm;                        // [64][404] hk tile, row-major
    float* Bsh = sm + 64 * ASH_PITCH;       // [2][16][68] dec_w tile, [h][o]
    float* wxk = Bsh + 2 * 16 * 68;         // [400]

    int tid = threadIdx.x;
    int k   = blockIdx.y;
    int n0  = blockIdx.x * 64;
    int tx = tid & 15, ty = tid >> 4;
    int lr = tid >> 2;          // 0..63
    int lc = (tid & 3) * 4;     // 0,4,8,12

    for (int h = tid; h < 400; h += 256) wxk[h] = dec_fc_w[h * 32 + 16 + k];
    __syncthreads();

    // build hk tile: relu(base + wxk), coalesced float4 loads + stores
    #pragma unroll 5
    for (int idx = tid; idx < 6400; idx += 256) {
        int n = idx / 100, c = (idx % 100) * 4;
        float4 v = *(const float4*)&g_base[(size_t)(n0 + n) * 400 + c];
        float* dst = &Ash[n * ASH_PITCH + c];
        dst[0] = fmaxf(v.x + wxk[c + 0], 0.f);
        dst[1] = fmaxf(v.y + wxk[c + 1], 0.f);
        dst[2] = fmaxf(v.z + wxk[c + 2], 0.f);
        dst[3] = fmaxf(v.w + wxk[c + 3], 0.f);
    }

    float acc[4] = {0.f, 0.f, 0.f, 0.f};

    auto ldb4 = [&](int o0, int hbase) -> float4 {
        if (o0 + lr < DIN)
            return *(const float4*)&dec_w[(size_t)(o0 + lr) * 400 + hbase + lc];
        return make_float4(0.f, 0.f, 0.f, 0.f);
    };
    auto stsB = [&](float* buf, float4 v) {
        buf[(lc + 0) * 68 + lr] = v.x;
        buf[(lc + 1) * 68 + lr] = v.y;
        buf[(lc + 2) * 68 + lr] = v.z;
        buf[(lc + 3) * 68 + lr] = v.w;
    };

    for (int ot = 0; ot < 13; ot++) {
        int o0 = ot * 64;
        float4 bv = ldb4(o0, 0);
        __syncthreads();          // covers Ash build (ot=0) and prev-tile readers
        stsB(Bsh, bv);
        __syncthreads();

        float c[4][4];
        #pragma unroll
        for (int r = 0; r < 4; r++)
            #pragma unroll
            for (int s = 0; s < 4; s++) c[r][s] = 0.f;

        for (int ht = 0; ht < 25; ht++) {
            float4 nv;
            if (ht < 24) nv = ldb4(o0, (ht + 1) * 16);
            const float* Bcur = Bsh + (ht & 1) * (16 * 68);
            const float* Arow0 = &Ash[(ty * 4 + 0) * ASH_PITCH + ht * 16];
            const float* Arow1 = &Ash[(ty * 4 + 1) * ASH_PITCH + ht * 16];
            const float* Arow2 = &Ash[(ty * 4 + 2) * ASH_PITCH + ht * 16];
            const float* Arow3 = &Ash[(ty * 4 + 3) * ASH_PITCH + ht * 16];
            #pragma unroll
            for (int kk = 0; kk < 16; kk++) {
                float4 b4 = *(const float4*)&Bcur[kk * 68 + tx * 4];
                float b_[4] = {b4.x, b4.y, b4.z, b4.w};
                float a_[4] = {Arow0[kk], Arow1[kk], Arow2[kk], Arow3[kk]};
                #pragma unroll
                for (int r = 0; r < 4; r++)
                    #pragma unroll
                    for (int s = 0; s < 4; s++)
                        c[r][s] = fmaf(a_[r], b_[s], c[r][s]);
            }
            if (ht < 24) {
                stsB(Bsh + ((ht + 1) & 1) * (16 * 68), nv);
                __syncthreads();
            }
        }

        // BCE epilogue for this o-tile
        int orow = o0 + tx * 4;
        if (orow < DIN) {
            float4 db = *(const float4*)&dec_b[orow];
            float bb[4] = {db.x, db.y, db.z, db.w};
            #pragma unroll
            for (int r = 0; r < 4; r++) {
                int n = n0 + ty * 4 + r;
                float4 yv = *(const float4*)&y[(size_t)n * DIN + orow];
                float yy[4] = {yv.x, yv.y, yv.z, yv.w};
                #pragma unroll
                for (int s = 0; s < 4; s++) {
                    float sv = c[r][s] + bb[s];
                    float t  = log1pf(expf(-fabsf(sv)));
                    float sp  = fminf(fmaxf(sv, 0.f) + t, 100.f);   // softplus(s)
                    float spm = fminf(fmaxf(-sv, 0.f) + t, 100.f);  // softplus(-s)
                    acc[r] += yy[s] * spm + (1.f - yy[s]) * sp;
                }
            }
        }
    }

    // reduce over tx (16 lanes) and write log_bk
    #pragma unroll
    for (int r = 0; r < 4; r++) {
        float v = acc[r];
        v += __shfl_xor_sync(0xffffffffu, v, 1, 16);
        v += __shfl_xor_sync(0xffffffffu, v, 2, 16);
        v += __shfl_xor_sync(0xffffffffu, v, 4, 16);
        v += __shfl_xor_sync(0xffffffffu, v, 8, 16);
        if (tx == 0)
            g_logbk[(size_t)(n0 + ty * 4 + r) * KST + k] = -v * (1.0f / 100.0f);
    }
}

// ---------------- HMM forward/backward + gamma ----------------
__global__ void fb_kernel(float* __restrict__ gamma_out) {
    int b = blockIdx.x;
    int tid = threadIdx.x;
    int lane = tid & 31, wid = tid >> 5;
    __shared__ float lAs[256];
    for (int i = tid; i < 256; i += 64) lAs[i] = g_lA[i];
    __syncthreads();
    const float* lb = g_logbk + (size_t)b * TLEN * KST;

    if (wid == 0 && lane < 16) {            // forward; lane = j
        int j = lane;
        float lacol[16];
        #pragma unroll
        for (int i = 0; i < 16; i++) lacol[i] = lAs[i * 16 + j];
        float prev = g_lp[j] + lb[j];
        g_alpha[((size_t)b * 128 + 0) * 16 + j] = prev;
        for (int t = 1; t < 128; t++) {
            float v[16]; float m = -1e30f;
            #pragma unroll
            for (int i = 0; i < 16; i++) {
                v[i] = __shfl_sync(0xffffu, prev, i, 16) + lacol[i];
                m = fmaxf(m, v[i]);
            }
            float s = 0.f;
            #pragma unroll
            for (int i = 0; i < 16; i++) s += expf(v[i] - m);
            prev = m + logf(s) + lb[t * 16 + j];
            g_alpha[((size_t)b * 128 + t) * 16 + j] = prev;
        }
    } else if (wid == 1 && lane < 16) {     // backward; lane = i
        int i = lane;
        float larow[16];
        #pragma unroll
        for (int j = 0; j < 16; j++) larow[j] = lAs[i * 16 + j];
        float bprev = 0.f;
        g_beta[((size_t)b * 128 + 127) * 16 + i] = 0.f;
        for (int t = 126; t >= 0; t--) {
            float w = bprev + lb[(t + 1) * 16 + i];  // lane i's contribution as state i
            float v[16]; float m = -1e30f;
            #pragma unroll
            for (int j = 0; j < 16; j++) {
                v[j] = __shfl_sync(0xffffu, w, j, 16) + larow[j];
                m = fmaxf(m, v[j]);
            }
            float s = 0.f;
            #pragma unroll
            for (int j = 0; j < 16; j++) s += expf(v[j] - m);
            bprev = m + logf(s);
            g_beta[((size_t)b * 128 + t) * 16 + i] = bprev;
        }
    }
    __syncthreads();

    // gamma: normalize alpha+beta over k (groups of 16 lanes)
    int kk = tid & 15;
    for (int t = tid >> 4; t < 128; t += 4) {
        size_t off = ((size_t)b * 128 + t) * 16 + kk;
        float lg = g_alpha[off] + g_beta[off];
        float m = lg;
        m = fmaxf(m, __shfl_xor_sync(0xffffffffu, m, 8, 16));
        m = fmaxf(m, __shfl_xor_sync(0xffffffffu, m, 4, 16));
        m = fmaxf(m, __shfl_xor_sync(0xffffffffu, m, 2, 16));
        m = fmaxf(m, __shfl_xor_sync(0xffffffffu, m, 1, 16));
        float e = expf(lg - m);
        float s = e;
        s += __shfl_xor_sync(0xffffffffu, s, 8, 16);
        s += __shfl_xor_sync(0xffffffffu, s, 4, 16);
        s += __shfl_xor_sync(0xffffffffu, s, 2, 16);
        s += __shfl_xor_sync(0xffffffffu, s, 1, 16);
        gamma_out[off] = e / s;
    }
}

// ---------------- xi ----------------
__global__ void xi_kernel(float* __restrict__ xi_out) {
    int t = blockIdx.x;    // 0..126
    int b = blockIdx.y;
    int tid = threadIdx.x; // 256
    int i = tid >> 4, j = tid & 15;
    int lane = tid & 31, wid = tid >> 5;

    float v = g_alpha[((size_t)b * 128 + t) * 16 + i] + g_lA[i * 16 + j]
            + g_logbk[((size_t)b * 128 + t + 1) * 16 + j]
            + g_beta [((size_t)b * 128 + t + 1) * 16 + j];

    __shared__ float rbuf[8];
    float m = v;
    #pragma unroll
    for (int off = 16; off >= 1; off >>= 1)
        m = fmaxf(m, __shfl_xor_sync(0xffffffffu, m, off));
    if (lane == 0) rbuf[wid] = m;
    __syncthreads();
    float bm = rbuf[0];
    #pragma unroll
    for (int w = 1; w < 8; w++) bm = fmaxf(bm, rbuf[w]);
    __syncthreads();

    float e = expf(v - bm);
    float s = e;
    #pragma unroll
    for (int off = 16; off >= 1; off >>= 1)
        s += __shfl_xor_sync(0xffffffffu, s, off);
    if (lane == 0) rbuf[wid] = s;
    __syncthreads();
    float bs = 0.f;
    #pragma unroll
    for (int w = 0; w < 8; w++) bs += rbuf[w];

    xi_out[(((size_t)b * 127 + t) * 256) + tid] = e / bs;
}

// ---------------- host launcher ----------------
static float *p_h = nullptr, *p_ml = nullptr, *p_z = nullptr, *p_base = nullptr;

static bool init_once() {
    cudaGetSymbolAddress((void**)&p_h, g_h);
    cudaGetSymbolAddress((void**)&p_ml, g_ml);
    cudaGetSymbolAddress((void**)&p_z, g_z);
    cudaGetSymbolAddress((void**)&p_base, g_base);
    cudaFuncSetAttribute(dec_bce, cudaFuncAttributeMaxDynamicSharedMemorySize,
                         DEC_SMEM_BYTES);
    return true;
}

extern "C" void kernel_launch(void* const* d_in, const int* in_sizes, int n_in,
                              void* d_out, int out_size) {
    (void)in_sizes; (void)n_in; (void)out_size;
    const float* y        = (const float*)d_in[0];
    const float* enc_w1   = (const float*)d_in[1];
    const float* enc_b1   = (const float*)d_in[2];
    const float* enc_w2   = (const float*)d_in[3];
    const float* enc_b2   = (const float*)d_in[4];
    const float* dec_fc_w = (const float*)d_in[5];
    const float* dec_fc_b = (const float*)d_in[6];
    const float* dec_w    = (const float*)d_in[7];
    const float* dec_b    = (const float*)d_in[8];
    const float* log_pi   = (const float*)d_in[9];
    const float* log_A    = (const float*)d_in[10];
    const float* eps      = (const float*)d_in[11];
    float* out = (float*)d_out;
    float* gamma_out = out;                       // [32,128,16]
    float* xi_out    = out + BSZ * TLEN * KST;    // [32,127,16,16]

    static bool once = init_once();
    (void)once;

    prep_lplA<<<1, 32>>>(log_pi, log_A);
    // h = relu(y @ W1^T + b1)
    gemm64<<<dim3(64, 7), 256>>>(y, DIN, enc_w1, DIN, enc_b1, p_h, H1,
                                 NTOT, H1, DIN, 1);
    // ml = h @ W2^T + b2
    gemm64<<<dim3(64, 1), 256>>>(p_h, H1, enc_w2, H1, enc_b2, p_ml, 32,
                                 NTOT, 32, H1, 0);
    reparam_kernel<<<(NTOT * LDIM + 255) / 256, 256>>>(eps);
    // base = z @ Wz^T + dec_fc_b  (Wz = dec_fc_w[:, :16], ldb = 32)
    gemm64<<<dim3(64, 7), 256>>>(p_z, LDIM, dec_fc_w, 32, dec_fc_b, p_base, H1,
                                 NTOT, H1, LDIM, 0);
    dec_bce<<<dim3(64, 16), 256, DEC_SMEM_BYTES>>>(dec_fc_w, dec_w, dec_b, y);
    fb_kernel<<<BSZ, 64>>>(gamma_out);
    xi_kernel<<<dim3(127, BSZ), 256>>>(xi_out);
}

// round 2
// speedup vs baseline: 1.0226x; 1.0226x over previous
#include <cuda_runtime.h>
#include <math.h>

// ---------------- problem constants ----------------
#define NTOT 4096      // B*T
#define TLEN 128
#define BSZ  32
#define KST  16
#define LDIM 16
#define H1   400
#define DIN  784

// ---------------- scratch (device globals; no runtime alloc) ----------------
__device__ float g_h   [NTOT * H1];
__device__ float g_ml  [NTOT * 32];
__device__ float g_z   [NTOT * LDIM];
__device__ float g_base[NTOT * H1];
__device__ float g_logbk[NTOT * KST];          // [b][t][k]
__device__ float g_lA[KST * KST];
__device__ float g_lp[KST];
__device__ float g_alpha[BSZ * TLEN * KST];
__device__ float g_beta [BSZ * TLEN * KST];

// ---------------- packed f32x2 helpers ----------------
__device__ __forceinline__ void fma2(unsigned long long& c,
                                     unsigned long long a,
                                     unsigned long long b) {
    asm("fma.rn.f32x2 %0, %1, %2, %0;" : "+l"(c) : "l"(a), "l"(b));
}
__device__ __forceinline__ unsigned long long dup2(float f) {
    unsigned long long r;
    asm("mov.b64 %0, {%1, %1};" : "=l"(r) : "f"(f));
    return r;
}
__device__ __forceinline__ void unpack2(unsigned long long v, float& lo, float& hi) {
    asm("mov.b64 {%0, %1}, %2;" : "=f"(lo), "=f"(hi) : "l"(v));
}

// ---------------- small prep: lp, lA ----------------
__global__ void prep_lplA(const float* __restrict__ log_pi,
                          const float* __restrict__ log_A) {
    int t = threadIdx.x;
    if (t < 16) {
        float m = -1e30f;
        for (int j = 0; j < 16; j++) m = fmaxf(m, log_A[t * 16 + j]);
        float s = 0.f;
        for (int j = 0; j < 16; j++) s += expf(log_A[t * 16 + j] - m);
        for (int j = 0; j < 16; j++)
            g_lA[t * 16 + j] = logf(expf(log_A[t * 16 + j] - m) / s + 1e-9f);
    } else if (t == 16) {
        float m = -1e30f;
        for (int j = 0; j < 16; j++) m = fmaxf(m, log_pi[j]);
        float s = 0.f;
        for (int j = 0; j < 16; j++) s += expf(log_pi[j] - m);
        for (int j = 0; j < 16; j++)
            g_lp[j] = logf(expf(log_pi[j] - m) / s + 1e-9f);
    }
}

// ---------------- generic tiled GEMM: C = act(A @ B^T + bias) ----------------
__global__ __launch_bounds__(256) void gemm64(
    const float* __restrict__ A, int lda,
    const float* __restrict__ B, int ldb,
    const float* __restrict__ bias,
    float* __restrict__ C, int ldc,
    int M, int N, int K, int relu_flag)
{
    __shared__ float As[16][68];
    __shared__ float Bs[16][68];
    int tid = threadIdx.x;
    int tx = tid & 15, ty = tid >> 4;
    int m0 = blockIdx.x * 64, j0 = blockIdx.y * 64;
    int lr = tid >> 2;          // 0..63
    int lc = (tid & 3) * 4;     // 0,4,8,12

    float c[4][4];
    #pragma unroll
    for (int r = 0; r < 4; r++)
        #pragma unroll
        for (int s = 0; s < 4; s++) c[r][s] = 0.f;

    for (int kt = 0; kt < K; kt += 16) {
        float4 av = *(const float4*)&A[(size_t)(m0 + lr) * lda + kt + lc];
        float4 bv = make_float4(0.f, 0.f, 0.f, 0.f);
        if (j0 + lr < N)
            bv = *(const float4*)&B[(size_t)(j0 + lr) * ldb + kt + lc];
        __syncthreads();
        As[lc + 0][lr] = av.x; As[lc + 1][lr] = av.y;
        As[lc + 2][lr] = av.z; As[lc + 3][lr] = av.w;
        Bs[lc + 0][lr] = bv.x; Bs[lc + 1][lr] = bv.y;
        Bs[lc + 2][lr] = bv.z; Bs[lc + 3][lr] = bv.w;
        __syncthreads();
        #pragma unroll
        for (int kk = 0; kk < 16; kk++) {
            float4 a4 = *(const float4*)&As[kk][ty * 4];
            float4 b4 = *(const float4*)&Bs[kk][tx * 4];
            float a_[4] = {a4.x, a4.y, a4.z, a4.w};
            float b_[4] = {b4.x, b4.y, b4.z, b4.w};
            #pragma unroll
            for (int r = 0; r < 4; r++)
                #pragma unroll
                for (int s = 0; s < 4; s++)
                    c[r][s] = fmaf(a_[r], b_[s], c[r][s]);
        }
    }
    #pragma unroll
    for (int r = 0; r < 4; r++) {
        int m = m0 + ty * 4 + r;
        #pragma unroll
        for (int s = 0; s < 4; s++) {
            int j = j0 + tx * 4 + s;
            if (j < N) {
                float v = c[r][s] + bias[j];
                if (relu_flag) v = fmaxf(v, 0.f);
                C[(size_t)m * ldc + j] = v;
            }
        }
    }
}

// ---------------- reparameterization ----------------
__global__ void reparam_kernel(const float* __restrict__ eps) {
    int idx = blockIdx.x * blockDim.x + threadIdx.x;
    if (idx < NTOT * LDIM) {
        int n = idx >> 4, l = idx & 15;
        g_z[idx] = g_ml[n * 32 + l] + eps[idx] * expf(0.5f * g_ml[n * 32 + 16 + l]);
    }
}

// ---------------- fused decoder GEMM + BCE reduction (f32x2 packed) ----------
// grid (64, 16): blockIdx.x = n-tile (64 rows), blockIdx.y = k (mixture state)
// Ash transposed: [400 h][64 n]  ->  LDS.128 gives 4 row values = 2 packed u64
#define ASH_FLOATS (400 * 64)
#define BSH_FLOATS (2 * 16 * 68)
#define DEC_SMEM_FLOATS (ASH_FLOATS + BSH_FLOATS + 400)
#define DEC_SMEM_BYTES  (DEC_SMEM_FLOATS * 4)

__global__ __launch_bounds__(256, 2) void dec_bce(
    const float* __restrict__ dec_fc_w,
    const float* __restrict__ dec_w,
    const float* __restrict__ dec_b,
    const float* __restrict__ y)
{
    extern __shared__ float sm[];
    float* Ash = sm;                        // [400][64] hk tile, transposed
    float* Bsh = sm + ASH_FLOATS;           // [2][16][68] dec_w tile, [h][o]
    float* wxk = Bsh + BSH_FLOATS;          // [400]

    int tid = threadIdx.x;
    int k   = blockIdx.y;
    int n0  = blockIdx.x * 64;
    int tx = tid & 15, ty = tid >> 4;
    int lr = tid >> 2;          // 0..63
    int lc = (tid & 3) * 4;     // 0,4,8,12

    for (int h = tid; h < 400; h += 256) wxk[h] = dec_fc_w[h * 32 + 16 + k];
    __syncthreads();

    // build hk tile TRANSPOSED: Ash[h][n] = relu(base[n][h] + wxk[h])
    // lanes map n = tid&63 (conflict-free smem stores), cg = h-group
    {
        int n  = tid & 63;
        int cg0 = tid >> 6;                 // 0..3
        const float* brow = &g_base[(size_t)(n0 + n) * 400];
        #pragma unroll 4
        for (int i = 0; i < 25; i++) {
            int cg = cg0 + i * 4;           // 0..99
            int c = cg * 4;
            float4 v = *(const float4*)&brow[c];
            Ash[(c + 0) * 64 + n] = fmaxf(v.x + wxk[c + 0], 0.f);
            Ash[(c + 1) * 64 + n] = fmaxf(v.y + wxk[c + 1], 0.f);
            Ash[(c + 2) * 64 + n] = fmaxf(v.z + wxk[c + 2], 0.f);
            Ash[(c + 3) * 64 + n] = fmaxf(v.w + wxk[c + 3], 0.f);
        }
    }

    float acc[4] = {0.f, 0.f, 0.f, 0.f};

    auto ldb4 = [&](int o0, int hbase) -> float4 {
        if (o0 + lr < DIN)
            return *(const float4*)&dec_w[(size_t)(o0 + lr) * 400 + hbase + lc];
        return make_float4(0.f, 0.f, 0.f, 0.f);
    };
    auto stsB = [&](float* buf, float4 v) {
        buf[(lc + 0) * 68 + lr] = v.x;
        buf[(lc + 1) * 68 + lr] = v.y;
        buf[(lc + 2) * 68 + lr] = v.z;
        buf[(lc + 3) * 68 + lr] = v.w;
    };

    for (int ot = 0; ot < 13; ot++) {
        int o0 = ot * 64;
        float4 bv = ldb4(o0, 0);
        __syncthreads();          // covers Ash build (ot=0) and prev-tile readers
        stsB(Bsh, bv);
        __syncthreads();

        // packed accumulators: c2[p][s] = (c[2p][s], c[2p+1][s])
        unsigned long long c2[2][4];
        #pragma unroll
        for (int p = 0; p < 2; p++)
            #pragma unroll
            for (int s = 0; s < 4; s++) c2[p][s] = 0ull;

        for (int ht = 0; ht < 25; ht++) {
            float4 nv;
            if (ht < 24) nv = ldb4(o0, (ht + 1) * 16);
            const float* Bcur = Bsh + (ht & 1) * (16 * 68);
            const float* Acol = &Ash[(ht * 16) * 64 + ty * 4];
            #pragma unroll
            for (int kk = 0; kk < 16; kk++) {
                ulonglong2 av = *(const ulonglong2*)(Acol + kk * 64);
                float4 b4 = *(const float4*)&Bcur[kk * 68 + tx * 4];
                unsigned long long bd0 = dup2(b4.x);
                unsigned long long bd1 = dup2(b4.y);
                unsigned long long bd2 = dup2(b4.z);
                unsigned long long bd3 = dup2(b4.w);
                fma2(c2[0][0], av.x, bd0);
                fma2(c2[0][1], av.x, bd1);
                fma2(c2[0][2], av.x, bd2);
                fma2(c2[0][3], av.x, bd3);
                fma2(c2[1][0], av.y, bd0);
                fma2(c2[1][1], av.y, bd1);
                fma2(c2[1][2], av.y, bd2);
                fma2(c2[1][3], av.y, bd3);
            }
            if (ht < 24) {
                stsB(Bsh + ((ht + 1) & 1) * (16 * 68), nv);
                __syncthreads();
            }
        }

        // unpack and BCE epilogue for this o-tile
        float c[4][4];
        #pragma unroll
        for (int p = 0; p < 2; p++)
            #pragma unroll
            for (int s = 0; s < 4; s++)
                unpack2(c2[p][s], c[2 * p][s], c[2 * p + 1][s]);

        int orow = o0 + tx * 4;
        if (orow < DIN) {
            float4 db = *(const float4*)&dec_b[orow];
            float bb[4] = {db.x, db.y, db.z, db.w};
            #pragma unroll
            for (int r = 0; r < 4; r++) {
                int n = n0 + ty * 4 + r;
                float4 yv = *(const float4*)&y[(size_t)n * DIN + orow];
                float yy[4] = {yv.x, yv.y, yv.z, yv.w};
                #pragma unroll
                for (int s = 0; s < 4; s++) {
                    float sv = c[r][s] + bb[s];
                    float t  = log1pf(expf(-fabsf(sv)));
                    float sp  = fminf(fmaxf(sv, 0.f) + t, 100.f);   // softplus(s)
                    float spm = fminf(fmaxf(-sv, 0.f) + t, 100.f);  // softplus(-s)
                    acc[r] += yy[s] * spm + (1.f - yy[s]) * sp;
                }
            }
        }
    }

    // reduce over tx (16 lanes) and write log_bk
    #pragma unroll
    for (int r = 0; r < 4; r++) {
        float v = acc[r];
        v += __shfl_xor_sync(0xffffffffu, v, 1, 16);
        v += __shfl_xor_sync(0xffffffffu, v, 2, 16);
        v += __shfl_xor_sync(0xffffffffu, v, 4, 16);
        v += __shfl_xor_sync(0xffffffffu, v, 8, 16);
        if (tx == 0)
            g_logbk[(size_t)(n0 + ty * 4 + r) * KST + k] = -v * (1.0f / 100.0f);
    }
}

// ---------------- HMM forward/backward + gamma ----------------
__global__ void fb_kernel(float* __restrict__ gamma_out) {
    int b = blockIdx.x;
    int tid = threadIdx.x;
    int lane = tid & 31, wid = tid >> 5;
    __shared__ float lAs[256];
    for (int i = tid; i < 256; i += 64) lAs[i] = g_lA[i];
    __syncthreads();
    const float* lb = g_logbk + (size_t)b * TLEN * KST;

    if (wid == 0 && lane < 16) {            // forward; lane = j
        int j = lane;
        float lacol[16];
        #pragma unroll
        for (int i = 0; i < 16; i++) lacol[i] = lAs[i * 16 + j];
        float prev = g_lp[j] + lb[j];
        g_alpha[((size_t)b * 128 + 0) * 16 + j] = prev;
        for (int t = 1; t < 128; t++) {
            float v[16]; float m = -1e30f;
            #pragma unroll
            for (int i = 0; i < 16; i++) {
                v[i] = __shfl_sync(0xffffu, prev, i, 16) + lacol[i];
                m = fmaxf(m, v[i]);
            }
            float s = 0.f;
            #pragma unroll
            for (int i = 0; i < 16; i++) s += expf(v[i] - m);
            prev = m + logf(s) + lb[t * 16 + j];
            g_alpha[((size_t)b * 128 + t) * 16 + j] = prev;
        }
    } else if (wid == 1 && lane < 16) {     // backward; lane = i
        int i = lane;
        float larow[16];
        #pragma unroll
        for (int j = 0; j < 16; j++) larow[j] = lAs[i * 16 + j];
        float bprev = 0.f;
        g_beta[((size_t)b * 128 + 127) * 16 + i] = 0.f;
        for (int t = 126; t >= 0; t--) {
            float w = bprev + lb[(t + 1) * 16 + i];
            float v[16]; float m = -1e30f;
            #pragma unroll
            for (int j = 0; j < 16; j++) {
                v[j] = __shfl_sync(0xffffu, w, j, 16) + larow[j];
                m = fmaxf(m, v[j]);
            }
            float s = 0.f;
            #pragma unroll
            for (int j = 0; j < 16; j++) s += expf(v[j] - m);
            bprev = m + logf(s);
            g_beta[((size_t)b * 128 + t) * 16 + i] = bprev;
        }
    }
    __syncthreads();

    // gamma: normalize alpha+beta over k (groups of 16 lanes)
    int kk = tid & 15;
    for (int t = tid >> 4; t < 128; t += 4) {
        size_t off = ((size_t)b * 128 + t) * 16 + kk;
        float lg = g_alpha[off] + g_beta[off];
        float m = lg;
        m = fmaxf(m, __shfl_xor_sync(0xffffffffu, m, 8, 16));
        m = fmaxf(m, __shfl_xor_sync(0xffffffffu, m, 4, 16));
        m = fmaxf(m, __shfl_xor_sync(0xffffffffu, m, 2, 16));
        m = fmaxf(m, __shfl_xor_sync(0xffffffffu, m, 1, 16));
        float e = expf(lg - m);
        float s = e;
        s += __shfl_xor_sync(0xffffffffu, s, 8, 16);
        s += __shfl_xor_sync(0xffffffffu, s, 4, 16);
        s += __shfl_xor_sync(0xffffffffu, s, 2, 16);
        s += __shfl_xor_sync(0xffffffffu, s, 1, 16);
        gamma_out[off] = e / s;
    }
}

// ---------------- xi ----------------
__global__ void xi_kernel(float* __restrict__ xi_out) {
    int t = blockIdx.x;    // 0..126
    int b = blockIdx.y;
    int tid = threadIdx.x; // 256
    int i = tid >> 4, j = tid & 15;
    int lane = tid & 31, wid = tid >> 5;

    float v = g_alpha[((size_t)b * 128 + t) * 16 + i] + g_lA[i * 16 + j]
            + g_logbk[((size_t)b * 128 + t + 1) * 16 + j]
            + g_beta [((size_t)b * 128 + t + 1) * 16 + j];

    __shared__ float rbuf[8];
    float m = v;
    #pragma unroll
    for (int off = 16; off >= 1; off >>= 1)
        m = fmaxf(m, __shfl_xor_sync(0xffffffffu, m, off));
    if (lane == 0) rbuf[wid] = m;
    __syncthreads();
    float bm = rbuf[0];
    #pragma unroll
    for (int w = 1; w < 8; w++) bm = fmaxf(bm, rbuf[w]);
    __syncthreads();

    float e = expf(v - bm);
    float s = e;
    #pragma unroll
    for (int off = 16; off >= 1; off >>= 1)
        s += __shfl_xor_sync(0xffffffffu, s, off);
    if (lane == 0) rbuf[wid] = s;
    __syncthreads();
    float bs = 0.f;
    #pragma unroll
    for (int w = 0; w < 8; w++) bs += rbuf[w];

    xi_out[(((size_t)b * 127 + t) * 256) + tid] = e / bs;
}

// ---------------- host launcher ----------------
static float *p_h = nullptr, *p_ml = nullptr, *p_z = nullptr, *p_base = nullptr;

static bool init_once() {
    cudaGetSymbolAddress((void**)&p_h, g_h);
    cudaGetSymbolAddress((void**)&p_ml, g_ml);
    cudaGetSymbolAddress((void**)&p_z, g_z);
    cudaGetSymbolAddress((void**)&p_base, g_base);
    cudaFuncSetAttribute(dec_bce, cudaFuncAttributeMaxDynamicSharedMemorySize,
                         DEC_SMEM_BYTES);
    return true;
}

extern "C" void kernel_launch(void* const* d_in, const int* in_sizes, int n_in,
                              void* d_out, int out_size) {
    (void)in_sizes; (void)n_in; (void)out_size;
    const float* y        = (const float*)d_in[0];
    const float* enc_w1   = (const float*)d_in[1];
    const float* enc_b1   = (const float*)d_in[2];
    const float* enc_w2   = (const float*)d_in[3];
    const float* enc_b2   = (const float*)d_in[4];
    const float* dec_fc_w = (const float*)d_in[5];
    const float* dec_fc_b = (const float*)d_in[6];
    const float* dec_w    = (const float*)d_in[7];
    const float* dec_b    = (const float*)d_in[8];
    const float* log_pi   = (const float*)d_in[9];
    const float* log_A    = (const float*)d_in[10];
    const float* eps      = (const float*)d_in[11];
    float* out = (float*)d_out;
    float* gamma_out = out;                       // [32,128,16]
    float* xi_out    = out + BSZ * TLEN * KST;    // [32,127,16,16]

    static bool once = init_once();
    (void)once;

    prep_lplA<<<1, 32>>>(log_pi, log_A);
    gemm64<<<dim3(64, 7), 256>>>(y, DIN, enc_w1, DIN, enc_b1, p_h, H1,
                                 NTOT, H1, DIN, 1);
    gemm64<<<dim3(64, 1), 256>>>(p_h, H1, enc_w2, H1, enc_b2, p_ml, 32,
                                 NTOT, 32, H1, 0);
    reparam_kernel<<<(NTOT * LDIM + 255) / 256, 256>>>(eps);
    gemm64<<<dim3(64, 7), 256>>>(p_z, LDIM, dec_fc_w, 32, dec_fc_b, p_base, H1,
                                 NTOT, H1, LDIM, 0);
    dec_bce<<<dim3(64, 16), 256, DEC_SMEM_BYTES>>>(dec_fc_w, dec_w, dec_b, y);
    fb_kernel<<<BSZ, 64>>>(gamma_out);
    xi_kernel<<<dim3(127, BSZ), 256>>>(xi_out);
}

// round 5
// speedup vs baseline: 1.0768x; 1.0530x over previous
#include <cuda_runtime.h>
#include <math.h>
#include <stdint.h>
#include <mma.h>

using namespace nvcuda;

// ---------------- problem constants ----------------
#define NTOT 4096      // B*T
#define TLEN 128
#define BSZ  32
#define KST  16
#define LDIM 16
#define H1   400
#define DIN  784

// ---------------- scratch (device globals; no runtime alloc) ----------------
__device__ float g_h   [NTOT * H1];
__device__ float g_ml  [NTOT * 32];
__device__ float g_z   [NTOT * LDIM];
__device__ float g_base[NTOT * H1];
__device__ float g_logbk[NTOT * KST];          // [b][t][k]
__device__ float g_lA[KST * KST];
__device__ float g_lp[KST];
__device__ float g_alpha[BSZ * TLEN * KST];
__device__ float g_beta [BSZ * TLEN * KST];

// ---------------- small prep: lp, lA ----------------
__global__ void prep_lplA(const float* __restrict__ log_pi,
                          const float* __restrict__ log_A) {
    int t = threadIdx.x;
    if (t < 16) {
        float m = -1e30f;
        for (int j = 0; j < 16; j++) m = fmaxf(m, log_A[t * 16 + j]);
        float s = 0.f;
        for (int j = 0; j < 16; j++) s += expf(log_A[t * 16 + j] - m);
        for (int j = 0; j < 16; j++)
            g_lA[t * 16 + j] = logf(expf(log_A[t * 16 + j] - m) / s + 1e-9f);
    } else if (t == 16) {
        float m = -1e30f;
        for (int j = 0; j < 16; j++) m = fmaxf(m, log_pi[j]);
        float s = 0.f;
        for (int j = 0; j < 16; j++) s += expf(log_pi[j] - m);
        for (int j = 0; j < 16; j++)
            g_lp[j] = logf(expf(log_pi[j] - m) / s + 1e-9f);
    }
}

// ---------------- generic tiled GEMM: C = act(A @ B^T + bias) ----------------
__global__ __launch_bounds__(256) void gemm64(
    const float* __restrict__ A, int lda,
    const float* __restrict__ B, int ldb,
    const float* __restrict__ bias,
    float* __restrict__ C, int ldc,
    int M, int N, int K, int relu_flag)
{
    __shared__ float As[16][68];
    __shared__ float Bs[16][68];
    int tid = threadIdx.x;
    int tx = tid & 15, ty = tid >> 4;
    int m0 = blockIdx.x * 64, j0 = blockIdx.y * 64;
    int lr = tid >> 2;
    int lc = (tid & 3) * 4;

    float c[4][4];
    #pragma unroll
    for (int r = 0; r < 4; r++)
        #pragma unroll
        for (int s = 0; s < 4; s++) c[r][s] = 0.f;

    for (int kt = 0; kt < K; kt += 16) {
        float4 av = *(const float4*)&A[(size_t)(m0 + lr) * lda + kt + lc];
        float4 bv = make_float4(0.f, 0.f, 0.f, 0.f);
        if (j0 + lr < N)
            bv = *(const float4*)&B[(size_t)(j0 + lr) * ldb + kt + lc];
        __syncthreads();
        As[lc + 0][lr] = av.x; As[lc + 1][lr] = av.y;
        As[lc + 2][lr] = av.z; As[lc + 3][lr] = av.w;
        Bs[lc + 0][lr] = bv.x; Bs[lc + 1][lr] = bv.y;
        Bs[lc + 2][lr] = bv.z; Bs[lc + 3][lr] = bv.w;
        __syncthreads();
        #pragma unroll
        for (int kk = 0; kk < 16; kk++) {
            float4 a4 = *(const float4*)&As[kk][ty * 4];
            float4 b4 = *(const float4*)&Bs[kk][tx * 4];
            float a_[4] = {a4.x, a4.y, a4.z, a4.w};
            float b_[4] = {b4.x, b4.y, b4.z, b4.w};
            #pragma unroll
            for (int r = 0; r < 4; r++)
                #pragma unroll
                for (int s = 0; s < 4; s++)
                    c[r][s] = fmaf(a_[r], b_[s], c[r][s]);
        }
    }
    #pragma unroll
    for (int r = 0; r < 4; r++) {
        int m = m0 + ty * 4 + r;
        #pragma unroll
        for (int s = 0; s < 4; s++) {
            int j = j0 + tx * 4 + s;
            if (j < N) {
                float v = c[r][s] + bias[j];
                if (relu_flag) v = fmaxf(v, 0.f);
                C[(size_t)m * ldc + j] = v;
            }
        }
    }
}

// ---------------- encoder layer1 via wmma tf32 ----------------
// h = relu(y @ enc_w1^T + b1): C[n, c] = y[n,:784] . w1[c,:784]
// grid (32, 5), 256 thr. warp w: rows (bx*8+w)*16, cols by*80..+79 (5 frags).
#define E1PITCH 84
__global__ __launch_bounds__(256) void enc1_wmma(
    const float* __restrict__ y,
    const float* __restrict__ w1,
    const float* __restrict__ b1)
{
    __shared__ float scr[8 * 16 * E1PITCH];
    int tid = threadIdx.x, wid = tid >> 5, lane = tid & 31;
    int r0 = (blockIdx.x * 8 + wid) * 16;
    int c0 = blockIdx.y * 80;

    wmma::fragment<wmma::accumulator, 16, 16, 8, float> c[5];
    wmma::fragment<wmma::matrix_a, 16, 16, 8, wmma::precision::tf32, wmma::row_major> a;
    wmma::fragment<wmma::matrix_b, 16, 16, 8, wmma::precision::tf32, wmma::col_major> b;
    #pragma unroll
    for (int j = 0; j < 5; j++) wmma::fill_fragment(c[j], 0.f);

    for (int ks = 0; ks < 98; ks++) {
        wmma::load_matrix_sync(a, y + (size_t)r0 * 784 + ks * 8, 784);
        #pragma unroll
        for (int e = 0; e < a.num_elements; e++) a.x[e] = wmma::__float_to_tf32(a.x[e]);
        #pragma unroll
        for (int j = 0; j < 5; j++) {
            wmma::load_matrix_sync(b, w1 + (size_t)(c0 + j * 16) * 784 + ks * 8, 784);
            #pragma unroll
            for (int e = 0; e < b.num_elements; e++) b.x[e] = wmma::__float_to_tf32(b.x[e]);
            wmma::mma_sync(c[j], a, b, c[j]);
        }
    }
    float* ws = scr + wid * 16 * E1PITCH;
    #pragma unroll
    for (int j = 0; j < 5; j++)
        wmma::store_matrix_sync(ws + j * 16, c[j], E1PITCH, wmma::mem_row_major);
    __syncwarp();
    for (int e = lane; e < 16 * 80; e += 32) {
        int r = e / 80, cc = e % 80;
        float v = ws[r * E1PITCH + cc] + b1[c0 + cc];
        g_h[(size_t)(r0 + r) * 400 + c0 + cc] = fmaxf(v, 0.f);
    }
}

// ---------------- reparameterization ----------------
__global__ void reparam_kernel(const float* __restrict__ eps) {
    int idx = blockIdx.x * blockDim.x + threadIdx.x;
    if (idx < NTOT * LDIM) {
        int n = idx >> 4, l = idx & 15;
        g_z[idx] = g_ml[n * 32 + l] + eps[idx] * expf(0.5f * g_ml[n * 32 + 16 + l]);
    }
}

// =============== fused decoder GEMM (wmma tf32) + MUFU-free BCE =============
// grid (64, 16): blockIdx.x = n-tile (64 rows), blockIdx.y = k (state).
// C[o, n] = dec_w[o,:400] . hk[n,:400];  hk staged in smem (matrix_b col-major)
// warp w handles o-tiles w, w+8, ... (49 tiles of 16); 4 n-tiles per o-tile.
#define APITCH 408
#define DEC_SMEM_FLOATS (64 * APITCH + 8 * 16 * 68 + 8 * 64 + 400 + 784)
#define DEC_SMEM_BYTES  (DEC_SMEM_FLOATS * 4)

__device__ __forceinline__ float softplus_poly(float sv, float& lnq_out) {
    // ln(1 + e^{-|sv|}) with zero MUFU:
    // w = -|sv|*log2e (clamped), 2^w = 2^i * 2^f (deg-8 Taylor), then Cephes log.
    float w = fmaxf(-fabsf(sv) * 1.4426950408889634f, -30.0f);
    float fi = floorf(w);
    float f = w - fi;
    float t = f * 0.6931471805599453f;
    float p = 1.f / 40320.f;
    p = fmaf(p, t, 1.f / 5040.f);
    p = fmaf(p, t, 1.f / 720.f);
    p = fmaf(p, t, 1.f / 120.f);
    p = fmaf(p, t, 1.f / 24.f);
    p = fmaf(p, t, 1.f / 6.f);
    p = fmaf(p, t, 0.5f);
    p = fmaf(p, t, 1.0f);
    p = fmaf(p, t, 1.0f);
    int ei = (int)fi;
    float sc = __int_as_float((unsigned)(ei + 127) << 23);
    float q = fmaf(p, sc, 1.0f);          // q = 1 + 2^w, in (1, 2]
    // ln(q): halve range if q > sqrt(2)
    bool hi = q > 1.41421356237f;
    float qr = hi ? 0.5f * q : q;
    float z = qr - 1.0f;                  // z in (-0.293, 0.414]
    float z2 = z * z;
    float pp = 7.0376836292e-2f;
    pp = fmaf(pp, z, -1.1514610310e-1f);
    pp = fmaf(pp, z, 1.1676998740e-1f);
    pp = fmaf(pp, z, -1.2420140846e-1f);
    pp = fmaf(pp, z, 1.4249322787e-1f);
    pp = fmaf(pp, z, -1.6668057665e-1f);
    pp = fmaf(pp, z, 2.0000714765e-1f);
    pp = fmaf(pp, z, -2.4999993993e-1f);
    pp = fmaf(pp, z, 3.3333331174e-1f);
    float lnq = fmaf(z2 * z, pp, fmaf(-0.5f, z2, z));
    if (hi) lnq += 0.6931471805599453f;
    lnq_out = lnq;
    return lnq;
}

__global__ __launch_bounds__(256, 1) void dec_bce_wmma(
    const float* __restrict__ dec_fc_w,
    const float* __restrict__ dec_w,
    const float* __restrict__ dec_b,
    const float* __restrict__ y)
{
    extern __shared__ float sm[];
    float* hk   = sm;                        // [64][408] (n, h) row-major
    float* scr  = sm + 64 * APITCH;          // per-warp [16][68]
    float* accw = scr + 8 * 16 * 68;         // [8][64]
    float* wxk  = accw + 8 * 64;             // [400]
    float* decb = wxk + 400;                 // [784]

    int tid = threadIdx.x, wid = tid >> 5, lane = tid & 31;
    int k  = blockIdx.y;
    int n0 = blockIdx.x * 64;

    for (int h = tid; h < 400; h += 256) wxk[h] = dec_fc_w[h * 32 + 16 + k];
    for (int o = tid; o < 784; o += 256) decb[o] = dec_b[o];
    __syncthreads();

    // build hk tile: hk[n][h] = relu(base[n0+n][h] + wxk[h])
    #pragma unroll 5
    for (int idx = tid; idx < 6400; idx += 256) {
        int n = idx / 100, c = (idx % 100) * 4;
        float4 v = *(const float4*)&g_base[(size_t)(n0 + n) * 400 + c];
        float* dst = &hk[n * APITCH + c];
        dst[0] = fmaxf(v.x + wxk[c + 0], 0.f);
        dst[1] = fmaxf(v.y + wxk[c + 1], 0.f);
        dst[2] = fmaxf(v.z + wxk[c + 2], 0.f);
        dst[3] = fmaxf(v.w + wxk[c + 3], 0.f);
    }
    __syncthreads();

    wmma::fragment<wmma::accumulator, 16, 16, 8, float> c[4];
    wmma::fragment<wmma::matrix_a, 16, 16, 8, wmma::precision::tf32, wmma::row_major> a;
    wmma::fragment<wmma::matrix_b, 16, 16, 8, wmma::precision::tf32, wmma::col_major> b;

    float* ws = scr + wid * 16 * 68;
    float accl0 = 0.f, accl1 = 0.f;

    for (int ot = wid; ot < 49; ot += 8) {
        int o0 = ot * 16;
        #pragma unroll
        for (int j = 0; j < 4; j++) wmma::fill_fragment(c[j], 0.f);

        for (int ks = 0; ks < 50; ks++) {
            wmma::load_matrix_sync(a, dec_w + (size_t)o0 * 400 + ks * 8, 400);
            #pragma unroll
            for (int e = 0; e < a.num_elements; e++)
                a.x[e] = wmma::__float_to_tf32(a.x[e]);
            #pragma unroll
            for (int nt = 0; nt < 4; nt++) {
                wmma::load_matrix_sync(b, hk + nt * 16 * APITCH + ks * 8, APITCH);
                #pragma unroll
                for (int e = 0; e < b.num_elements; e++)
                    b.x[e] = wmma::__float_to_tf32(b.x[e]);
                wmma::mma_sync(c[nt], a, b, c[nt]);
            }
        }
        #pragma unroll
        for (int nt = 0; nt < 4; nt++)
            wmma::store_matrix_sync(ws + nt * 16, c[nt], 68, wmma::mem_row_major);
        __syncwarp();

        // BCE epilogue (MUFU-free). ws[r][n] = s(o0+r, n0+n)
        #pragma unroll
        for (int h2 = 0; h2 < 2; h2++) {
            int n = lane + h2 * 32;
            const float* yrow = y + (size_t)(n0 + n) * DIN;
            float a0 = 0.f;
            #pragma unroll 4
            for (int r = 0; r < 16; r++) {
                int o = o0 + r;
                float sv = ws[r * 68 + n] + decb[o];
                float yy = __ldg(&yrow[o]);
                float lnq;
                softplus_poly(sv, lnq);
                float sp  = fminf(fmaxf(sv, 0.f) + lnq, 100.f);
                float spm = fminf(fmaxf(-sv, 0.f) + lnq, 100.f);
                a0 += yy * spm + (1.f - yy) * sp;
            }
            if (h2 == 0) accl0 += a0; else accl1 += a0;
        }
        __syncwarp();
    }

    accw[wid * 64 + lane]      = accl0;
    accw[wid * 64 + lane + 32] = accl1;
    __syncthreads();
    if (tid < 64) {
        float s = 0.f;
        #pragma unroll
        for (int w = 0; w < 8; w++) s += accw[w * 64 + tid];
        g_logbk[(size_t)(n0 + tid) * KST + k] = -s * 0.01f;
    }
}

// ---------------- HMM forward/backward + gamma ----------------
__global__ void fb_kernel(float* __restrict__ gamma_out) {
    int b = blockIdx.x;
    int tid = threadIdx.x;
    int lane = tid & 31, wid = tid >> 5;
    __shared__ float lAs[256];
    for (int i = tid; i < 256; i += 64) lAs[i] = g_lA[i];
    __syncthreads();
    const float* lb = g_logbk + (size_t)b * TLEN * KST;

    if (wid == 0 && lane < 16) {            // forward
        int j = lane;
        float lacol[16];
        #pragma unroll
        for (int i = 0; i < 16; i++) lacol[i] = lAs[i * 16 + j];
        float prev = g_lp[j] + lb[j];
        g_alpha[((size_t)b * 128 + 0) * 16 + j] = prev;
        for (int t = 1; t < 128; t++) {
            float v[16]; float m = -1e30f;
            #pragma unroll
            for (int i = 0; i < 16; i++) {
                v[i] = __shfl_sync(0xffffu, prev, i, 16) + lacol[i];
                m = fmaxf(m, v[i]);
            }
            float s = 0.f;
            #pragma unroll
            for (int i = 0; i < 16; i++) s += expf(v[i] - m);
            prev = m + logf(s) + lb[t * 16 + j];
            g_alpha[((size_t)b * 128 + t) * 16 + j] = prev;
        }
    } else if (wid == 1 && lane < 16) {     // backward
        int i = lane;
        float larow[16];
        #pragma unroll
        for (int j = 0; j < 16; j++) larow[j] = lAs[i * 16 + j];
        float bprev = 0.f;
        g_beta[((size_t)b * 128 + 127) * 16 + i] = 0.f;
        for (int t = 126; t >= 0; t--) {
            float w = bprev + lb[(t + 1) * 16 + i];
            float v[16]; float m = -1e30f;
            #pragma unroll
            for (int j = 0; j < 16; j++) {
                v[j] = __shfl_sync(0xffffu, w, j, 16) + larow[j];
                m = fmaxf(m, v[j]);
            }
            float s = 0.f;
            #pragma unroll
            for (int j = 0; j < 16; j++) s += expf(v[j] - m);
            bprev = m + logf(s);
            g_beta[((size_t)b * 128 + t) * 16 + i] = bprev;
        }
    }
    __syncthreads();

    int kk = tid & 15;
    for (int t = tid >> 4; t < 128; t += 4) {
        size_t off = ((size_t)b * 128 + t) * 16 + kk;
        float lg = g_alpha[off] + g_beta[off];
        float m = lg;
        m = fmaxf(m, __shfl_xor_sync(0xffffffffu, m, 8, 16));
        m = fmaxf(m, __shfl_xor_sync(0xffffffffu, m, 4, 16));
        m = fmaxf(m, __shfl_xor_sync(0xffffffffu, m, 2, 16));
        m = fmaxf(m, __shfl_xor_sync(0xffffffffu, m, 1, 16));
        float e = expf(lg - m);
        float s = e;
        s += __shfl_xor_sync(0xffffffffu, s, 8, 16);
        s += __shfl_xor_sync(0xffffffffu, s, 4, 16);
        s += __shfl_xor_sync(0xffffffffu, s, 2, 16);
        s += __shfl_xor_sync(0xffffffffu, s, 1, 16);
        gamma_out[off] = e / s;
    }
}

// ---------------- xi ----------------
__global__ void xi_kernel(float* __restrict__ xi_out) {
    int t = blockIdx.x;    // 0..126
    int b = blockIdx.y;
    int tid = threadIdx.x; // 256
    int i = tid >> 4, j = tid & 15;
    int lane = tid & 31, wid = tid >> 5;

    float v = g_alpha[((size_t)b * 128 + t) * 16 + i] + g_lA[i * 16 + j]
            + g_logbk[((size_t)b * 128 + t + 1) * 16 + j]
            + g_beta [((size_t)b * 128 + t + 1) * 16 + j];

    __shared__ float rbuf[8];
    float m = v;
    #pragma unroll
    for (int off = 16; off >= 1; off >>= 1)
        m = fmaxf(m, __shfl_xor_sync(0xffffffffu, m, off));
    if (lane == 0) rbuf[wid] = m;
    __syncthreads();
    float bm = rbuf[0];
    #pragma unroll
    for (int w = 1; w < 8; w++) bm = fmaxf(bm, rbuf[w]);
    __syncthreads();

    float e = expf(v - bm);
    float s = e;
    #pragma unroll
    for (int off = 16; off >= 1; off >>= 1)
        s += __shfl_xor_sync(0xffffffffu, s, off);
    if (lane == 0) rbuf[wid] = s;
    __syncthreads();
    float bs = 0.f;
    #pragma unroll
    for (int w = 0; w < 8; w++) bs += rbuf[w];

    xi_out[(((size_t)b * 127 + t) * 256) + tid] = e / bs;
}

// ---------------- host launcher ----------------
static float *p_h = nullptr, *p_ml = nullptr, *p_z = nullptr, *p_base = nullptr;

static bool init_once() {
    cudaGetSymbolAddress((void**)&p_h, g_h);
    cudaGetSymbolAddress((void**)&p_ml, g_ml);
    cudaGetSymbolAddress((void**)&p_z, g_z);
    cudaGetSymbolAddress((void**)&p_base, g_base);
    cudaFuncSetAttribute(dec_bce_wmma, cudaFuncAttributeMaxDynamicSharedMemorySize,
                         DEC_SMEM_BYTES);
    return true;
}

extern "C" void kernel_launch(void* const* d_in, const int* in_sizes, int n_in,
                              void* d_out, int out_size) {
    (void)in_sizes; (void)n_in; (void)out_size;
    const float* y        = (const float*)d_in[0];
    const float* enc_w1   = (const float*)d_in[1];
    const float* enc_b1   = (const float*)d_in[2];
    const float* enc_w2   = (const float*)d_in[3];
    const float* enc_b2   = (const float*)d_in[4];
    const float* dec_fc_w = (const float*)d_in[5];
    const float* dec_fc_b = (const float*)d_in[6];
    const float* dec_w    = (const float*)d_in[7];
    const float* dec_b    = (const float*)d_in[8];
    const float* log_pi   = (const float*)d_in[9];
    const float* log_A    = (const float*)d_in[10];
    const float* eps      = (const float*)d_in[11];
    float* out = (float*)d_out;
    float* gamma_out = out;                       // [32,128,16]
    float* xi_out    = out + BSZ * TLEN * KST;    // [32,127,16,16]

    static bool once = init_once();
    (void)once;

    prep_lplA<<<1, 32>>>(log_pi, log_A);
    // h = relu(y @ W1^T + b1)  via wmma tf32
    enc1_wmma<<<dim3(32, 5), 256>>>(y, enc_w1, enc_b1);
    // ml = h @ W2^T + b2
    gemm64<<<dim3(64, 1), 256>>>(p_h, H1, enc_w2, H1, enc_b2, p_ml, 32,
                                 NTOT, 32, H1, 0);
    reparam_kernel<<<(NTOT * LDIM + 255) / 256, 256>>>(eps);
    // base = z @ Wz^T + dec_fc_b
    gemm64<<<dim3(64, 7), 256>>>(p_z, LDIM, dec_fc_w, 32, dec_fc_b, p_base, H1,
                                 NTOT, H1, LDIM, 0);
    dec_bce_wmma<<<dim3(64, 16), 256, DEC_SMEM_BYTES>>>(dec_fc_w, dec_w, dec_b, y);
    fb_kernel<<<BSZ, 64>>>(gamma_out);
    xi_kernel<<<dim3(127, BSZ), 256>>>(xi_out);
}

// round 6
// speedup vs baseline: 1.2703x; 1.1797x over previous
#include <cuda_runtime.h>
#include <math.h>
#include <stdint.h>
#include <mma.h>

using namespace nvcuda;

// ---------------- problem constants ----------------
#define NTOT 4096      // B*T
#define TLEN 128
#define BSZ  32
#define KST  16
#define LDIM 16
#define H1   400
#define DIN  784

// ---------------- scratch (device globals; no runtime alloc) ----------------
__device__ float g_h   [NTOT * H1];
__device__ float g_ml  [NTOT * 32];
__device__ float g_z   [NTOT * LDIM];
__device__ float g_base[NTOT * H1];
__device__ float g_wT  [H1 * DIN];             // dec_w transposed + tf32-rounded
__device__ float g_logbk[NTOT * KST];          // [b][t][k]
__device__ float g_lA[KST * KST];
__device__ float g_lp[KST];
__device__ float g_alpha[BSZ * TLEN * KST];
__device__ float g_beta [BSZ * TLEN * KST];

// ---------------- small prep: lp, lA ----------------
__global__ void prep_lplA(const float* __restrict__ log_pi,
                          const float* __restrict__ log_A) {
    int t = threadIdx.x;
    if (t < 16) {
        float m = -1e30f;
        for (int j = 0; j < 16; j++) m = fmaxf(m, log_A[t * 16 + j]);
        float s = 0.f;
        for (int j = 0; j < 16; j++) s += expf(log_A[t * 16 + j] - m);
        for (int j = 0; j < 16; j++)
            g_lA[t * 16 + j] = logf(expf(log_A[t * 16 + j] - m) / s + 1e-9f);
    } else if (t == 16) {
        float m = -1e30f;
        for (int j = 0; j < 16; j++) m = fmaxf(m, log_pi[j]);
        float s = 0.f;
        for (int j = 0; j < 16; j++) s += expf(log_pi[j] - m);
        for (int j = 0; j < 16; j++)
            g_lp[j] = logf(expf(log_pi[j] - m) / s + 1e-9f);
    }
}

// ---------------- dec_w transpose + tf32 round ----------------
__global__ void transpose_w(const float* __restrict__ dec_w) {
    __shared__ float t[32][33];
    int hx = blockIdx.x * 32;   // h tile base
    int oy = blockIdx.y * 32;   // o tile base
    int tx = threadIdx.x, ty = threadIdx.y;   // (32, 8)
    for (int r = ty; r < 32; r += 8) {
        int o = oy + r, h = hx + tx;
        t[r][tx] = (o < DIN && h < H1) ? dec_w[o * H1 + h] : 0.f;
    }
    __syncthreads();
    for (int r = ty; r < 32; r += 8) {
        int h = hx + r, o = oy + tx;
        if (h < H1 && o < DIN)
            g_wT[h * DIN + o] = wmma::__float_to_tf32(t[tx][r]);
    }
}

// ---------------- generic tiled GEMM: C = act(A @ B^T + bias) ----------------
__global__ __launch_bounds__(256) void gemm64(
    const float* __restrict__ A, int lda,
    const float* __restrict__ B, int ldb,
    const float* __restrict__ bias,
    float* __restrict__ C, int ldc,
    int M, int N, int K, int relu_flag)
{
    __shared__ float As[16][68];
    __shared__ float Bs[16][68];
    int tid = threadIdx.x;
    int tx = tid & 15, ty = tid >> 4;
    int m0 = blockIdx.x * 64, j0 = blockIdx.y * 64;
    int lr = tid >> 2;
    int lc = (tid & 3) * 4;

    float c[4][4];
    #pragma unroll
    for (int r = 0; r < 4; r++)
        #pragma unroll
        for (int s = 0; s < 4; s++) c[r][s] = 0.f;

    for (int kt = 0; kt < K; kt += 16) {
        float4 av = *(const float4*)&A[(size_t)(m0 + lr) * lda + kt + lc];
        float4 bv = make_float4(0.f, 0.f, 0.f, 0.f);
        if (j0 + lr < N)
            bv = *(const float4*)&B[(size_t)(j0 + lr) * ldb + kt + lc];
        __syncthreads();
        As[lc + 0][lr] = av.x; As[lc + 1][lr] = av.y;
        As[lc + 2][lr] = av.z; As[lc + 3][lr] = av.w;
        Bs[lc + 0][lr] = bv.x; Bs[lc + 1][lr] = bv.y;
        Bs[lc + 2][lr] = bv.z; Bs[lc + 3][lr] = bv.w;
        __syncthreads();
        #pragma unroll
        for (int kk = 0; kk < 16; kk++) {
            float4 a4 = *(const float4*)&As[kk][ty * 4];
            float4 b4 = *(const float4*)&Bs[kk][tx * 4];
            float a_[4] = {a4.x, a4.y, a4.z, a4.w};
            float b_[4] = {b4.x, b4.y, b4.z, b4.w};
            #pragma unroll
            for (int r = 0; r < 4; r++)
                #pragma unroll
                for (int s = 0; s < 4; s++)
                    c[r][s] = fmaf(a_[r], b_[s], c[r][s]);
        }
    }
    #pragma unroll
    for (int r = 0; r < 4; r++) {
        int m = m0 + ty * 4 + r;
        #pragma unroll
        for (int s = 0; s < 4; s++) {
            int j = j0 + tx * 4 + s;
            if (j < N) {
                float v = c[r][s] + bias[j];
                if (relu_flag) v = fmaxf(v, 0.f);
                C[(size_t)m * ldc + j] = v;
            }
        }
    }
}

// ---------------- encoder layer1 via wmma tf32 ----------------
#define E1PITCH 84
__global__ __launch_bounds__(256) void enc1_wmma(
    const float* __restrict__ y,
    const float* __restrict__ w1,
    const float* __restrict__ b1)
{
    __shared__ float scr[8 * 16 * E1PITCH];
    int tid = threadIdx.x, wid = tid >> 5, lane = tid & 31;
    int r0 = (blockIdx.x * 8 + wid) * 16;
    int c0 = blockIdx.y * 80;

    wmma::fragment<wmma::accumulator, 16, 16, 8, float> c[5];
    wmma::fragment<wmma::matrix_a, 16, 16, 8, wmma::precision::tf32, wmma::row_major> a;
    wmma::fragment<wmma::matrix_b, 16, 16, 8, wmma::precision::tf32, wmma::col_major> b;
    #pragma unroll
    for (int j = 0; j < 5; j++) wmma::fill_fragment(c[j], 0.f);

    for (int ks = 0; ks < 98; ks++) {
        wmma::load_matrix_sync(a, y + (size_t)r0 * 784 + ks * 8, 784);
        #pragma unroll
        for (int e = 0; e < a.num_elements; e++) a.x[e] = wmma::__float_to_tf32(a.x[e]);
        #pragma unroll
        for (int j = 0; j < 5; j++) {
            wmma::load_matrix_sync(b, w1 + (size_t)(c0 + j * 16) * 784 + ks * 8, 784);
            #pragma unroll
            for (int e = 0; e < b.num_elements; e++) b.x[e] = wmma::__float_to_tf32(b.x[e]);
            wmma::mma_sync(c[j], a, b, c[j]);
        }
    }
    float* ws = scr + wid * 16 * E1PITCH;
    #pragma unroll
    for (int j = 0; j < 5; j++)
        wmma::store_matrix_sync(ws + j * 16, c[j], E1PITCH, wmma::mem_row_major);
    __syncwarp();
    for (int e = lane; e < 16 * 80; e += 32) {
        int r = e / 80, cc = e % 80;
        float v = ws[r * E1PITCH + cc] + b1[c0 + cc];
        g_h[(size_t)(r0 + r) * 400 + c0 + cc] = fmaxf(v, 0.f);
    }
}

// ---------------- reparameterization ----------------
__global__ void reparam_kernel(const float* __restrict__ eps) {
    int idx = blockIdx.x * blockDim.x + threadIdx.x;
    if (idx < NTOT * LDIM) {
        int n = idx >> 4, l = idx & 15;
        g_z[idx] = g_ml[n * 32 + l] + eps[idx] * expf(0.5f * g_ml[n * 32 + 16 + l]);
    }
}

// ---------------- MUFU-free softplus core: returns ln(1+e^{-|sv|}) ----------
__device__ __forceinline__ float softplus_tail(float sv) {
    float w = fmaxf(-fabsf(sv) * 1.4426950408889634f, -30.0f);
    float fi = floorf(w);
    float f = w - fi;
    float t = f * 0.6931471805599453f;
    float p = 1.f / 40320.f;
    p = fmaf(p, t, 1.f / 5040.f);
    p = fmaf(p, t, 1.f / 720.f);
    p = fmaf(p, t, 1.f / 120.f);
    p = fmaf(p, t, 1.f / 24.f);
    p = fmaf(p, t, 1.f / 6.f);
    p = fmaf(p, t, 0.5f);
    p = fmaf(p, t, 1.0f);
    p = fmaf(p, t, 1.0f);
    int ei = (int)fi;
    float sc = __int_as_float((unsigned)(ei + 127) << 23);
    float q = fmaf(p, sc, 1.0f);          // 1 + 2^w, in (1, 2]
    bool hi = q > 1.41421356237f;
    float qr = hi ? 0.5f * q : q;
    float z = qr - 1.0f;
    float z2 = z * z;
    float pp = 7.0376836292e-2f;
    pp = fmaf(pp, z, -1.1514610310e-1f);
    pp = fmaf(pp, z, 1.1676998740e-1f);
    pp = fmaf(pp, z, -1.2420140846e-1f);
    pp = fmaf(pp, z, 1.4249322787e-1f);
    pp = fmaf(pp, z, -1.6668057665e-1f);
    pp = fmaf(pp, z, 2.0000714765e-1f);
    pp = fmaf(pp, z, -2.4999993993e-1f);
    pp = fmaf(pp, z, 3.3333331174e-1f);
    float lnq = fmaf(z2 * z, pp, fmaf(-0.5f, z2, z));
    if (hi) lnq += 0.6931471805599453f;
    return lnq;
}
__device__ __forceinline__ float bce_term(float sv, float yy) {
    float lnq = softplus_tail(sv);
    float sp  = fminf(fmaxf(sv, 0.f) + lnq, 100.f);
    float spm = fminf(fmaxf(-sv, 0.f) + lnq, 100.f);
    return yy * spm + (1.f - yy) * sp;
}

// =============== fused decoder GEMM (wmma tf32, clean smem) + BCE ===========
// grid (64, 16): blockIdx.x = n-tile (64), blockIdx.y = k.
// hk (A) in smem pitch 404 (conflict-free a-ldm); dec_wT (B) staged coalesced
// into smem pitch 260 (conflict-free b-ldm), 40-row double-buffered stages.
// o-chunks of 256 (warp = 64n x 32o); C scratch overlays B buffers.
#define APITCH 404
#define BPITCH 260
#define KC     40
#define UN_FLOATS (2 * KC * BPITCH)       // 20800 (>= Cs 64*260 = 16640)
#define DEC2_FLOATS (64 * APITCH + UN_FLOATS + 784 + 400)
#define DEC2_SMEM   (DEC2_FLOATS * 4)     // 191,360 B

__global__ __launch_bounds__(256, 1) void dec_bce_wmma2(
    const float* __restrict__ dec_fc_w,
    const float* __restrict__ dec_b,
    const float* __restrict__ y)
{
    extern __shared__ float sm[];
    float* hk   = sm;                       // [64][404]
    float* un   = sm + 64 * APITCH;         // B double-buffer / C scratch
    float* decb = un + UN_FLOATS;           // [784]
    float* wxk  = decb + 784;               // [400]

    int tid = threadIdx.x, wid = tid >> 5;
    int k  = blockIdx.y;
    int n0 = blockIdx.x * 64;

    for (int h = tid; h < 400; h += 256) wxk[h] = dec_fc_w[h * 32 + 16 + k];
    for (int o = tid; o < 784; o += 256) decb[o] = dec_b[o];
    __syncthreads();

    // build hk (tf32-rounded): hk[n][h] = tf32(relu(base[n0+n][h] + wxk[h]))
    #pragma unroll 5
    for (int idx = tid; idx < 6400; idx += 256) {
        int n = idx / 100, c = (idx % 100) * 4;
        float4 v = *(const float4*)&g_base[(size_t)(n0 + n) * 400 + c];
        float* dst = &hk[n * APITCH + c];
        dst[0] = wmma::__float_to_tf32(fmaxf(v.x + wxk[c + 0], 0.f));
        dst[1] = wmma::__float_to_tf32(fmaxf(v.y + wxk[c + 1], 0.f));
        dst[2] = wmma::__float_to_tf32(fmaxf(v.z + wxk[c + 2], 0.f));
        dst[3] = wmma::__float_to_tf32(fmaxf(v.w + wxk[c + 3], 0.f));
    }
    __syncthreads();

    float acc = 0.f;
    int owarp = wid * 32;

    // cooperative B stage: rows [s*KC, s*KC+40) x cols [o0, o0+256) -> buf
    auto stage_B = [&](int s, int o0) {
        float* bb = un + (s & 1) * (KC * BPITCH);
        #pragma unroll
        for (int i = 0; i < 10; i++) {
            int f4 = tid + i * 256;             // 0..2559
            int row = f4 >> 6;                  // 64 float4 per row
            int c4 = (f4 & 63) * 4;
            int o = o0 + c4;
            float4 v = make_float4(0.f, 0.f, 0.f, 0.f);
            if (o < DIN)
                v = *(const float4*)&g_wT[(size_t)(s * KC + row) * DIN + o];
            *(float4*)&bb[row * BPITCH + c4] = v;
        }
    };

    for (int oc = 0; oc < 4; oc++) {
        int o0 = oc * 256;
        int ow = (o0 + 256 <= DIN) ? 256 : (DIN - o0);   // 256,256,256,16
        bool wactive = owarp < ow;

        stage_B(0, o0);
        __syncthreads();

        wmma::fragment<wmma::accumulator, 16, 16, 8, float> c[4][2];
        #pragma unroll
        for (int nt = 0; nt < 4; nt++)
            #pragma unroll
            for (int hf = 0; hf < 2; hf++) wmma::fill_fragment(c[nt][hf], 0.f);

        for (int st = 0; st < 10; st++) {
            if (st < 9) stage_B(st + 1, o0);
            if (wactive) {
                const float* Bst = un + (st & 1) * (KC * BPITCH);
                #pragma unroll
                for (int ksl = 0; ksl < 5; ksl++) {
                    int kk = st * KC + ksl * 8;
                    wmma::fragment<wmma::matrix_a, 16, 16, 8,
                                   wmma::precision::tf32, wmma::row_major> a[4];
                    wmma::fragment<wmma::matrix_b, 16, 16, 8,
                                   wmma::precision::tf32, wmma::row_major> b0, b1;
                    #pragma unroll
                    for (int nt = 0; nt < 4; nt++)
                        wmma::load_matrix_sync(a[nt], hk + nt * 16 * APITCH + kk, APITCH);
                    wmma::load_matrix_sync(b0, Bst + ksl * 8 * BPITCH + owarp, BPITCH);
                    wmma::load_matrix_sync(b1, Bst + ksl * 8 * BPITCH + owarp + 16, BPITCH);
                    #pragma unroll
                    for (int nt = 0; nt < 4; nt++) {
                        wmma::mma_sync(c[nt][0], a[nt], b0, c[nt][0]);
                        wmma::mma_sync(c[nt][1], a[nt], b1, c[nt][1]);
                    }
                }
            }
            __syncthreads();
        }

        // C -> scratch (overlays B buffers; mainloop fully synced above)
        if (wactive) {
            #pragma unroll
            for (int nt = 0; nt < 4; nt++)
                #pragma unroll
                for (int hf = 0; hf < 2; hf++)
                    wmma::store_matrix_sync(un + nt * 16 * BPITCH + owarp + hf * 16,
                                            c[nt][hf], BPITCH, wmma::mem_row_major);
        }
        __syncthreads();

        // BCE epilogue: thread -> (n = tid>>2, o-range (tid&3)*64)
        {
            int n = tid >> 2;
            int ob = (tid & 3) * 64;
            const float* yrow = y + (size_t)(n0 + n) * DIN + o0;
            const float* crow = &un[n * BPITCH];
            for (int j = 0; j < 64; j += 4) {
                int o = ob + j;
                if (o >= ow) break;
                float4 cv = *(const float4*)&crow[o];
                float4 yv = *(const float4*)&yrow[o];
                float4 db = *(const float4*)&decb[o0 + o];
                acc += bce_term(cv.x + db.x, yv.x);
                acc += bce_term(cv.y + db.y, yv.y);
                acc += bce_term(cv.z + db.z, yv.z);
                acc += bce_term(cv.w + db.w, yv.w);
            }
        }
        __syncthreads();   // scratch reads done before next oc's staging
    }

    // combine 4 threads per n (consecutive lanes) and write
    acc += __shfl_xor_sync(0xffffffffu, acc, 1, 4);
    acc += __shfl_xor_sync(0xffffffffu, acc, 2, 4);
    if ((tid & 3) == 0)
        g_logbk[(size_t)(n0 + (tid >> 2)) * KST + k] = -acc * 0.01f;
}

// ---------------- HMM forward/backward + gamma ----------------
__global__ void fb_kernel(float* __restrict__ gamma_out) {
    int b = blockIdx.x;
    int tid = threadIdx.x;
    int lane = tid & 31, wid = tid >> 5;
    __shared__ float lAs[256];
    for (int i = tid; i < 256; i += 64) lAs[i] = g_lA[i];
    __syncthreads();
    const float* lb = g_logbk + (size_t)b * TLEN * KST;

    if (wid == 0 && lane < 16) {            // forward
        int j = lane;
        float lacol[16];
        #pragma unroll
        for (int i = 0; i < 16; i++) lacol[i] = lAs[i * 16 + j];
        float prev = g_lp[j] + lb[j];
        g_alpha[((size_t)b * 128 + 0) * 16 + j] = prev;
        for (int t = 1; t < 128; t++) {
            float v[16]; float m = -1e30f;
            #pragma unroll
            for (int i = 0; i < 16; i++) {
                v[i] = __shfl_sync(0xffffu, prev, i, 16) + lacol[i];
                m = fmaxf(m, v[i]);
            }
            float s = 0.f;
            #pragma unroll
            for (int i = 0; i < 16; i++) s += expf(v[i] - m);
            prev = m + logf(s) + lb[t * 16 + j];
            g_alpha[((size_t)b * 128 + t) * 16 + j] = prev;
        }
    } else if (wid == 1 && lane < 16) {     // backward
        int i = lane;
        float larow[16];
        #pragma unroll
        for (int j = 0; j < 16; j++) larow[j] = lAs[i * 16 + j];
        float bprev = 0.f;
        g_beta[((size_t)b * 128 + 127) * 16 + i] = 0.f;
        for (int t = 126; t >= 0; t--) {
            float w = bprev + lb[(t + 1) * 16 + i];
            float v[16]; float m = -1e30f;
            #pragma unroll
            for (int j = 0; j < 16; j++) {
                v[j] = __shfl_sync(0xffffu, w, j, 16) + larow[j];
                m = fmaxf(m, v[j]);
            }
            float s = 0.f;
            #pragma unroll
            for (int j = 0; j < 16; j++) s += expf(v[j] - m);
            bprev = m + logf(s);
            g_beta[((size_t)b * 128 + t) * 16 + i] = bprev;
        }
    }
    __syncthreads();

    int kk = tid & 15;
    for (int t = tid >> 4; t < 128; t += 4) {
        size_t off = ((size_t)b * 128 + t) * 16 + kk;
        float lg = g_alpha[off] + g_beta[off];
        float m = lg;
        m = fmaxf(m, __shfl_xor_sync(0xffffffffu, m, 8, 16));
        m = fmaxf(m, __shfl_xor_sync(0xffffffffu, m, 4, 16));
        m = fmaxf(m, __shfl_xor_sync(0xffffffffu, m, 2, 16));
        m = fmaxf(m, __shfl_xor_sync(0xffffffffu, m, 1, 16));
        float e = expf(lg - m);
        float s = e;
        s += __shfl_xor_sync(0xffffffffu, s, 8, 16);
        s += __shfl_xor_sync(0xffffffffu, s, 4, 16);
        s += __shfl_xor_sync(0xffffffffu, s, 2, 16);
        s += __shfl_xor_sync(0xffffffffu, s, 1, 16);
        gamma_out[off] = e / s;
    }
}

// ---------------- xi ----------------
__global__ void xi_kernel(float* __restrict__ xi_out) {
    int t = blockIdx.x;    // 0..126
    int b = blockIdx.y;
    int tid = threadIdx.x; // 256
    int i = tid >> 4, j = tid & 15;
    int lane = tid & 31, wid = tid >> 5;

    float v = g_alpha[((size_t)b * 128 + t) * 16 + i] + g_lA[i * 16 + j]
            + g_logbk[((size_t)b * 128 + t + 1) * 16 + j]
            + g_beta [((size_t)b * 128 + t + 1) * 16 + j];

    __shared__ float rbuf[8];
    float m = v;
    #pragma unroll
    for (int off = 16; off >= 1; off >>= 1)
        m = fmaxf(m, __shfl_xor_sync(0xffffffffu, m, off));
    if (lane == 0) rbuf[wid] = m;
    __syncthreads();
    float bm = rbuf[0];
    #pragma unroll
    for (int w = 1; w < 8; w++) bm = fmaxf(bm, rbuf[w]);
    __syncthreads();

    float e = expf(v - bm);
    float s = e;
    #pragma unroll
    for (int off = 16; off >= 1; off >>= 1)
        s += __shfl_xor_sync(0xffffffffu, s, off);
    if (lane == 0) rbuf[wid] = s;
    __syncthreads();
    float bs = 0.f;
    #pragma unroll
    for (int w = 0; w < 8; w++) bs += rbuf[w];

    xi_out[(((size_t)b * 127 + t) * 256) + tid] = e / bs;
}

// ---------------- host launcher ----------------
static float *p_h = nullptr, *p_ml = nullptr, *p_z = nullptr, *p_base = nullptr;

static bool init_once() {
    cudaGetSymbolAddress((void**)&p_h, g_h);
    cudaGetSymbolAddress((void**)&p_ml, g_ml);
    cudaGetSymbolAddress((void**)&p_z, g_z);
    cudaGetSymbolAddress((void**)&p_base, g_base);
    cudaFuncSetAttribute(dec_bce_wmma2, cudaFuncAttributeMaxDynamicSharedMemorySize,
                         DEC2_SMEM);
    return true;
}

extern "C" void kernel_launch(void* const* d_in, const int* in_sizes, int n_in,
                              void* d_out, int out_size) {
    (void)in_sizes; (void)n_in; (void)out_size;
    const float* y        = (const float*)d_in[0];
    const float* enc_w1   = (const float*)d_in[1];
    const float* enc_b1   = (const float*)d_in[2];
    const float* enc_w2   = (const float*)d_in[3];
    const float* enc_b2   = (const float*)d_in[4];
    const float* dec_fc_w = (const float*)d_in[5];
    const float* dec_fc_b = (const float*)d_in[6];
    const float* dec_w    = (const float*)d_in[7];
    const float* dec_b    = (const float*)d_in[8];
    const float* log_pi   = (const float*)d_in[9];
    const float* log_A    = (const float*)d_in[10];
    const float* eps      = (const float*)d_in[11];
    float* out = (float*)d_out;
    float* gamma_out = out;                       // [32,128,16]
    float* xi_out    = out + BSZ * TLEN * KST;    // [32,127,16,16]

    static bool once = init_once();
    (void)once;

    prep_lplA<<<1, 32>>>(log_pi, log_A);
    transpose_w<<<dim3(13, 25), dim3(32, 8)>>>(dec_w);
    enc1_wmma<<<dim3(32, 5), 256>>>(y, enc_w1, enc_b1);
    gemm64<<<dim3(64, 1), 256>>>(p_h, H1, enc_w2, H1, enc_b2, p_ml, 32,
                                 NTOT, 32, H1, 0);
    reparam_kernel<<<(NTOT * LDIM + 255) / 256, 256>>>(eps);
    gemm64<<<dim3(64, 7), 256>>>(p_z, LDIM, dec_fc_w, 32, dec_fc_b, p_base, H1,
                                 NTOT, H1, LDIM, 0);
    dec_bce_wmma2<<<dim3(64, 16), 256, DEC2_SMEM>>>(dec_fc_w, dec_b, y);
    fb_kernel<<<BSZ, 64>>>(gamma_out);
    xi_kernel<<<dim3(127, BSZ), 256>>>(xi_out);
}

// round 13
// speedup vs baseline: 2.3390x; 1.8413x over previous
#include <cuda_runtime.h>
#include <cuda_fp16.h>
#include <math.h>
#include <stdint.h>
#include <mma.h>

using namespace nvcuda;

// ---------------- problem constants ----------------
#define NTOT 4096      // B*T
#define TLEN 128
#define BSZ  32
#define KST  16
#define LDIM 16
#define H1   400
#define DIN  784
#define WTP  800       // g_wTh padded row length (halves)

// ---------------- scratch (device globals; no runtime alloc) ----------------
__device__ float g_h   [NTOT * H1];
__device__ float g_ml  [NTOT * 32];
__device__ float g_z   [NTOT * LDIM];
__device__ float g_base[NTOT * H1];
__device__ __half g_wTh[H1 * WTP];             // dec_w transposed + fp16
__device__ float g_logbk[NTOT * KST];          // [b][t][k]
__device__ float g_lA[KST * KST];
__device__ float g_lp[KST];
__device__ float g_alpha[BSZ * TLEN * KST];
__device__ float g_beta [BSZ * TLEN * KST];

// ---------------- small prep: lp, lA ----------------
__global__ void prep_lplA(const float* __restrict__ log_pi,
                          const float* __restrict__ log_A) {
    int t = threadIdx.x;
    if (t < 16) {
        float m = -1e30f;
        for (int j = 0; j < 16; j++) m = fmaxf(m, log_A[t * 16 + j]);
        float s = 0.f;
        for (int j = 0; j < 16; j++) s += expf(log_A[t * 16 + j] - m);
        for (int j = 0; j < 16; j++)
            g_lA[t * 16 + j] = logf(expf(log_A[t * 16 + j] - m) / s + 1e-9f);
    } else if (t == 16) {
        float m = -1e30f;
        for (int j = 0; j < 16; j++) m = fmaxf(m, log_pi[j]);
        float s = 0.f;
        for (int j = 0; j < 16; j++) s += expf(log_pi[j] - m);
        for (int j = 0; j < 16; j++)
            g_lp[j] = logf(expf(log_pi[j] - m) / s + 1e-9f);
    }
}

// ---------------- dec_w transpose + fp16 convert (zero-padded to WTP) -------
__global__ void transpose_w(const float* __restrict__ dec_w) {
    __shared__ float t[32][33];
    int hx = blockIdx.x * 32;   // h tile base
    int oy = blockIdx.y * 32;   // o tile base (0..800)
    int tx = threadIdx.x, ty = threadIdx.y;   // (32, 8)
    for (int r = ty; r < 32; r += 8) {
        int o = oy + r, h = hx + tx;
        t[r][tx] = (o < DIN && h < H1) ? dec_w[o * H1 + h] : 0.f;
    }
    __syncthreads();
    for (int r = ty; r < 32; r += 8) {
        int h = hx + r, o = oy + tx;
        if (h < H1 && o < WTP)
            g_wTh[h * WTP + o] = __float2half_rn(t[tx][r]);
    }
}

// ---------------- generic tiled GEMM: C = act(A @ B^T + bias) ----------------
__global__ __launch_bounds__(256) void gemm64(
    const float* __restrict__ A, int lda,
    const float* __restrict__ B, int ldb,
    const float* __restrict__ bias,
    float* __restrict__ C, int ldc,
    int M, int N, int K, int relu_flag)
{
    __shared__ float As[16][68];
    __shared__ float Bs[16][68];
    int tid = threadIdx.x;
    int tx = tid & 15, ty = tid >> 4;
    int m0 = blockIdx.x * 64, j0 = blockIdx.y * 64;
    int lr = tid >> 2;
    int lc = (tid & 3) * 4;

    float c[4][4];
    #pragma unroll
    for (int r = 0; r < 4; r++)
        #pragma unroll
        for (int s = 0; s < 4; s++) c[r][s] = 0.f;

    for (int kt = 0; kt < K; kt += 16) {
        float4 av = *(const float4*)&A[(size_t)(m0 + lr) * lda + kt + lc];
        float4 bv = make_float4(0.f, 0.f, 0.f, 0.f);
        if (j0 + lr < N)
            bv = *(const float4*)&B[(size_t)(j0 + lr) * ldb + kt + lc];
        __syncthreads();
        As[lc + 0][lr] = av.x; As[lc + 1][lr] = av.y;
        As[lc + 2][lr] = av.z; As[lc + 3][lr] = av.w;
        Bs[lc + 0][lr] = bv.x; Bs[lc + 1][lr] = bv.y;
        Bs[lc + 2][lr] = bv.z; Bs[lc + 3][lr] = bv.w;
        __syncthreads();
        #pragma unroll
        for (int kk = 0; kk < 16; kk++) {
            float4 a4 = *(const float4*)&As[kk][ty * 4];
            float4 b4 = *(const float4*)&Bs[kk][tx * 4];
            float a_[4] = {a4.x, a4.y, a4.z, a4.w};
            float b_[4] = {b4.x, b4.y, b4.z, b4.w};
            #pragma unroll
            for (int r = 0; r < 4; r++)
                #pragma unroll
                for (int s = 0; s < 4; s++)
                    c[r][s] = fmaf(a_[r], b_[s], c[r][s]);
        }
    }
    #pragma unroll
    for (int r = 0; r < 4; r++) {
        int m = m0 + ty * 4 + r;
        #pragma unroll
        for (int s = 0; s < 4; s++) {
            int j = j0 + tx * 4 + s;
            if (j < N) {
                float v = c[r][s] + bias[j];
                if (relu_flag) v = fmaxf(v, 0.f);
                C[(size_t)m * ldc + j] = v;
            }
        }
    }
}

// ---------------- encoder layer1 via wmma tf32 ----------------
#define E1PITCH 84
__global__ __launch_bounds__(256) void enc1_wmma(
    const float* __restrict__ y,
    const float* __restrict__ w1,
    const float* __restrict__ b1)
{
    __shared__ float scr[8 * 16 * E1PITCH];
    int tid = threadIdx.x, wid = tid >> 5, lane = tid & 31;
    int r0 = (blockIdx.x * 8 + wid) * 16;
    int c0 = blockIdx.y * 80;

    wmma::fragment<wmma::accumulator, 16, 16, 8, float> c[5];
    wmma::fragment<wmma::matrix_a, 16, 16, 8, wmma::precision::tf32, wmma::row_major> a;
    wmma::fragment<wmma::matrix_b, 16, 16, 8, wmma::precision::tf32, wmma::col_major> b;
    #pragma unroll
    for (int j = 0; j < 5; j++) wmma::fill_fragment(c[j], 0.f);

    for (int ks = 0; ks < 98; ks++) {
        wmma::load_matrix_sync(a, y + (size_t)r0 * 784 + ks * 8, 784);
        #pragma unroll
        for (int e = 0; e < a.num_elements; e++) a.x[e] = wmma::__float_to_tf32(a.x[e]);
        #pragma unroll
        for (int j = 0; j < 5; j++) {
            wmma::load_matrix_sync(b, w1 + (size_t)(c0 + j * 16) * 784 + ks * 8, 784);
            #pragma unroll
            for (int e = 0; e < b.num_elements; e++) b.x[e] = wmma::__float_to_tf32(b.x[e]);
            wmma::mma_sync(c[j], a, b, c[j]);
        }
    }
    float* ws = scr + wid * 16 * E1PITCH;
    #pragma unroll
    for (int j = 0; j < 5; j++)
        wmma::store_matrix_sync(ws + j * 16, c[j], E1PITCH, wmma::mem_row_major);
    __syncwarp();
    for (int e = lane; e < 16 * 80; e += 32) {
        int r = e / 80, cc = e % 80;
        float v = ws[r * E1PITCH + cc] + b1[c0 + cc];
        g_h[(size_t)(r0 + r) * 400 + c0 + cc] = fmaxf(v, 0.f);
    }
}

// ---------------- reparameterization ----------------
__global__ void reparam_kernel(const float* __restrict__ eps) {
    int idx = blockIdx.x * blockDim.x + threadIdx.x;
    if (idx < NTOT * LDIM) {
        int n = idx >> 4, l = idx & 15;
        g_z[idx] = g_ml[n * 32 + l] + eps[idx] * expf(0.5f * g_ml[n * 32 + 16 + l]);
    }
}

// ---------------- MUFU-free softplus core: returns ln(1+e^{-|sv|}) ----------
__device__ __forceinline__ float softplus_tail(float sv) {
    float w = fmaxf(-fabsf(sv) * 1.4426950408889634f, -30.0f);
    float fi = floorf(w);
    float f = w - fi;
    float t = f * 0.6931471805599453f;
    float p = 1.f / 40320.f;
    p = fmaf(p, t, 1.f / 5040.f);
    p = fmaf(p, t, 1.f / 720.f);
    p = fmaf(p, t, 1.f / 120.f);
    p = fmaf(p, t, 1.f / 24.f);
    p = fmaf(p, t, 1.f / 6.f);
    p = fmaf(p, t, 0.5f);
    p = fmaf(p, t, 1.0f);
    p = fmaf(p, t, 1.0f);
    int ei = (int)fi;
    float sc = __int_as_float((unsigned)(ei + 127) << 23);
    float q = fmaf(p, sc, 1.0f);          // 1 + 2^w, in (1, 2]
    bool hi = q > 1.41421356237f;
    float qr = hi ? 0.5f * q : q;
    float z = qr - 1.0f;
    float z2 = z * z;
    float pp = 7.0376836292e-2f;
    pp = fmaf(pp, z, -1.1514610310e-1f);
    pp = fmaf(pp, z, 1.1676998740e-1f);
    pp = fmaf(pp, z, -1.2420140846e-1f);
    pp = fmaf(pp, z, 1.4249322787e-1f);
    pp = fmaf(pp, z, -1.6668057665e-1f);
    pp = fmaf(pp, z, 2.0000714765e-1f);
    pp = fmaf(pp, z, -2.4999993993e-1f);
    pp = fmaf(pp, z, 3.3333331174e-1f);
    float lnq = fmaf(z2 * z, pp, fmaf(-0.5f, z2, z));
    if (hi) lnq += 0.6931471805599453f;
    return lnq;
}
__device__ __forceinline__ float bce_term(float sv, float yy) {
    float lnq = softplus_tail(sv);
    float sp  = fminf(fmaxf(sv, 0.f) + lnq, 100.f);
    float spm = fminf(fmaxf(-sv, 0.f) + lnq, 100.f);
    return yy * spm + (1.f - yy) * sp;
}

// =============== fused decoder GEMM (wmma fp16, LDSM) + BCE =================
// grid (64, 16): blockIdx.x = n-tile (64), blockIdx.y = k.
// hk (A) half pitch 408 (conflict-free LDSM); g_wTh (B) staged as half,
// pitch 264 (conflict-free LDSM.T), KC=80-row double-buffered stages.
// o-chunks of 256 (warp = 64n x 32o); fp32 C scratch overlays B buffers.
#define APITCH_H 408
#define BPITCH_H 264
#define KC       80
#define HK_BYTES (64 * APITCH_H * 2)                  // 52224
#define BBUF_BYTES (KC * BPITCH_H * 2)                // 42240 per buffer
#define CPITCH   260
#define UN_BYTES (2 * BBUF_BYTES)                     // 84480 (> Cs 66560)
#define DEC3_SMEM (HK_BYTES + UN_BYTES + 784 * 4 + 400 * 4)   // 141,440

__global__ __launch_bounds__(256, 1) void dec_bce_half(
    const float* __restrict__ dec_fc_w,
    const float* __restrict__ dec_b,
    const float* __restrict__ y)
{
    extern __shared__ char smc[];
    __half* hk  = (__half*)smc;                       // [64][408] halves
    char*   un  = smc + HK_BYTES;                     // B bufs / C scratch
    float*  Cs  = (float*)un;                         // [64][260]
    float* decb = (float*)(un + UN_BYTES);            // [784]
    float* wxk  = decb + 784;                         // [400]

    int tid = threadIdx.x, wid = tid >> 5;
    int k  = blockIdx.y;
    int n0 = blockIdx.x * 64;

    for (int h = tid; h < 400; h += 256) wxk[h] = dec_fc_w[h * 32 + 16 + k];
    for (int o = tid; o < 784; o += 256) decb[o] = dec_b[o];
    __syncthreads();

    // build hk (half): hk[n][h] = half(relu(base[n0+n][h] + wxk[h]))
    #pragma unroll 5
    for (int idx = tid; idx < 6400; idx += 256) {
        int n = idx / 100, c = (idx % 100) * 4;
        float4 v = *(const float4*)&g_base[(size_t)(n0 + n) * 400 + c];
        __half2* dst = (__half2*)&hk[n * APITCH_H + c];
        dst[0] = __floats2half2_rn(fmaxf(v.x + wxk[c + 0], 0.f),
                                   fmaxf(v.y + wxk[c + 1], 0.f));
        dst[1] = __floats2half2_rn(fmaxf(v.z + wxk[c + 2], 0.f),
                                   fmaxf(v.w + wxk[c + 3], 0.f));
    }
    __syncthreads();

    float acc = 0.f;
    int owarp = wid * 32;

    // cooperative B stage: rows [s*KC, s*KC+80) x cols [o0, o0+256) halves
    auto stage_B = [&](int s, int o0) {
        __half* bb = (__half*)(un + (s & 1) * BBUF_BYTES);
        #pragma unroll
        for (int i = 0; i < 10; i++) {
            int u = tid + i * 256;            // 0..2559
            int row = u >> 5;                 // 32 uint4 (16B) per row
            int c8 = (u & 31) * 8;            // halves
            int o = o0 + c8;
            uint4 v = make_uint4(0u, 0u, 0u, 0u);
            if (o < DIN)
                v = *(const uint4*)&g_wTh[(size_t)(s * KC + row) * WTP + o];
            *(uint4*)&bb[row * BPITCH_H + c8] = v;
        }
    };

    for (int oc = 0; oc < 4; oc++) {
        int o0 = oc * 256;
        int ow = (o0 + 256 <= DIN) ? 256 : (DIN - o0);   // 256,256,256,16
        bool wactive = owarp < ow;

        stage_B(0, o0);
        __syncthreads();

        wmma::fragment<wmma::accumulator, 16, 16, 16, float> c[4][2];
        #pragma unroll
        for (int nt = 0; nt < 4; nt++)
            #pragma unroll
            for (int hf = 0; hf < 2; hf++) wmma::fill_fragment(c[nt][hf], 0.f);

        for (int st = 0; st < 5; st++) {
            if (st < 4) stage_B(st + 1, o0);
            if (wactive) {
                const __half* Bst = (const __half*)(un + (st & 1) * BBUF_BYTES);
                #pragma unroll
                for (int ksl = 0; ksl < 5; ksl++) {
                    int kk = st * KC + ksl * 16;
                    wmma::fragment<wmma::matrix_a, 16, 16, 16, __half,
                                   wmma::row_major> a[4];
                    wmma::fragment<wmma::matrix_b, 16, 16, 16, __half,
                                   wmma::row_major> b0, b1;
                    #pragma unroll
                    for (int nt = 0; nt < 4; nt++)
                        wmma::load_matrix_sync(a[nt], hk + nt * 16 * APITCH_H + kk,
                                               APITCH_H);
                    wmma::load_matrix_sync(b0, Bst + (ksl * 16) * BPITCH_H + owarp,
                                           BPITCH_H);
                    wmma::load_matrix_sync(b1, Bst + (ksl * 16) * BPITCH_H + owarp + 16,
                                           BPITCH_H);
                    #pragma unroll
                    for (int nt = 0; nt < 4; nt++) {
                        wmma::mma_sync(c[nt][0], a[nt], b0, c[nt][0]);
                        wmma::mma_sync(c[nt][1], a[nt], b1, c[nt][1]);
                    }
                }
            }
            __syncthreads();
        }

        // C -> scratch (overlays B buffers; mainloop fully synced above)
        if (wactive) {
            #pragma unroll
            for (int nt = 0; nt < 4; nt++)
                #pragma unroll
                for (int hf = 0; hf < 2; hf++)
                    wmma::store_matrix_sync(Cs + nt * 16 * CPITCH + owarp + hf * 16,
                                            c[nt][hf], CPITCH, wmma::mem_row_major);
        }
        __syncthreads();

        // BCE epilogue: thread -> (n = tid>>2, o-range (tid&3)*64)
        {
            int n = tid >> 2;
            int ob = (tid & 3) * 64;
            const float* yrow = y + (size_t)(n0 + n) * DIN + o0;
            const float* crow = &Cs[n * CPITCH];
            for (int j = 0; j < 64; j += 4) {
                int o = ob + j;
                if (o >= ow) break;
                float4 cv = *(const float4*)&crow[o];
                float4 yv = *(const float4*)&yrow[o];
                float4 db = *(const float4*)&decb[o0 + o];
                acc += bce_term(cv.x + db.x, yv.x);
                acc += bce_term(cv.y + db.y, yv.y);
                acc += bce_term(cv.z + db.z, yv.z);
                acc += bce_term(cv.w + db.w, yv.w);
            }
        }
        __syncthreads();   // scratch reads done before next oc's staging
    }

    // combine 4 threads per n (consecutive lanes) and write
    acc += __shfl_xor_sync(0xffffffffu, acc, 1, 4);
    acc += __shfl_xor_sync(0xffffffffu, acc, 2, 4);
    if ((tid & 3) == 0)
        g_logbk[(size_t)(n0 + (tid >> 2)) * KST + k] = -acc * 0.01f;
}

// ---------------- HMM forward/backward + gamma ----------------
__global__ void fb_kernel(float* __restrict__ gamma_out) {
    int b = blockIdx.x;
    int tid = threadIdx.x;
    int lane = tid & 31, wid = tid >> 5;
    __shared__ float lAs[256];
    for (int i = tid; i < 256; i += 64) lAs[i] = g_lA[i];
    __syncthreads();
    const float* lb = g_logbk + (size_t)b * TLEN * KST;

    if (wid == 0 && lane < 16) {            // forward
        int j = lane;
        float lacol[16];
        #pragma unroll
        for (int i = 0; i < 16; i++) lacol[i] = lAs[i * 16 + j];
        float prev = g_lp[j] + lb[j];
        g_alpha[((size_t)b * 128 + 0) * 16 + j] = prev;
        for (int t = 1; t < 128; t++) {
            float v[16]; float m = -1e30f;
            #pragma unroll
            for (int i = 0; i < 16; i++) {
                v[i] = __shfl_sync(0xffffu, prev, i, 16) + lacol[i];
                m = fmaxf(m, v[i]);
            }
            float s = 0.f;
            #pragma unroll
            for (int i = 0; i < 16; i++) s += expf(v[i] - m);
            prev = m + logf(s) + lb[t * 16 + j];
            g_alpha[((size_t)b * 128 + t) * 16 + j] = prev;
        }
    } else if (wid == 1 && lane < 16) {     // backward
        int i = lane;
        float larow[16];
        #pragma unroll
        for (int j = 0; j < 16; j++) larow[j] = lAs[i * 16 + j];
        float bprev = 0.f;
        g_beta[((size_t)b * 128 + 127) * 16 + i] = 0.f;
        for (int t = 126; t >= 0; t--) {
            float w = bprev + lb[(t + 1) * 16 + i];
            float v[16]; float m = -1e30f;
            #pragma unroll
            for (int j = 0; j < 16; j++) {
                v[j] = __shfl_sync(0xffffu, w, j, 16) + larow[j];
                m = fmaxf(m, v[j]);
            }
            float s = 0.f;
            #pragma unroll
            for (int j = 0; j < 16; j++) s += expf(v[j] - m);
            bprev = m + logf(s);
            g_beta[((size_t)b * 128 + t) * 16 + i] = bprev;
        }
    }
    __syncthreads();

    int kk = tid & 15;
    for (int t = tid >> 4; t < 128; t += 4) {
        size_t off = ((size_t)b * 128 + t) * 16 + kk;
        float lg = g_alpha[off] + g_beta[off];
        float m = lg;
        m = fmaxf(m, __shfl_xor_sync(0xffffffffu, m, 8, 16));
        m = fmaxf(m, __shfl_xor_sync(0xffffffffu, m, 4, 16));
        m = fmaxf(m, __shfl_xor_sync(0xffffffffu, m, 2, 16));
        m = fmaxf(m, __shfl_xor_sync(0xffffffffu, m, 1, 16));
        float e = expf(lg - m);
        float s = e;
        s += __shfl_xor_sync(0xffffffffu, s, 8, 16);
        s += __shfl_xor_sync(0xffffffffu, s, 4, 16);
        s += __shfl_xor_sync(0xffffffffu, s, 2, 16);
        s += __shfl_xor_sync(0xffffffffu, s, 1, 16);
        gamma_out[off] = e / s;
    }
}

// ---------------- xi ----------------
__global__ void xi_kernel(float* __restrict__ xi_out) {
    int t = blockIdx.x;    // 0..126
    int b = blockIdx.y;
    int tid = threadIdx.x; // 256
    int i = tid >> 4, j = tid & 15;
    int lane = tid & 31, wid = tid >> 5;

    float v = g_alpha[((size_t)b * 128 + t) * 16 + i] + g_lA[i * 16 + j]
            + g_logbk[((size_t)b * 128 + t + 1) * 16 + j]
            + g_beta [((size_t)b * 128 + t + 1) * 16 + j];

    __shared__ float rbuf[8];
    float m = v;
    #pragma unroll
    for (int off = 16; off >= 1; off >>= 1)
        m = fmaxf(m, __shfl_xor_sync(0xffffffffu, m, off));
    if (lane == 0) rbuf[wid] = m;
    __syncthreads();
    float bm = rbuf[0];
    #pragma unroll
    for (int w = 1; w < 8; w++) bm = fmaxf(bm, rbuf[w]);
    __syncthreads();

    float e = expf(v - bm);
    float s = e;
    #pragma unroll
    for (int off = 16; off >= 1; off >>= 1)
        s += __shfl_xor_sync(0xffffffffu, s, off);
    if (lane == 0) rbuf[wid] = s;
    __syncthreads();
    float bs = 0.f;
    #pragma unroll
    for (int w = 0; w < 8; w++) bs += rbuf[w];

    xi_out[(((size_t)b * 127 + t) * 256) + tid] = e / bs;
}

// ---------------- host launcher ----------------
static float *p_h = nullptr, *p_ml = nullptr, *p_z = nullptr, *p_base = nullptr;

static bool init_once() {
    cudaGetSymbolAddress((void**)&p_h, g_h);
    cudaGetSymbolAddress((void**)&p_ml, g_ml);
    cudaGetSymbolAddress((void**)&p_z, g_z);
    cudaGetSymbolAddress((void**)&p_base, g_base);
    cudaFuncSetAttribute(dec_bce_half, cudaFuncAttributeMaxDynamicSharedMemorySize,
                         DEC3_SMEM);
    return true;
}

extern "C" void kernel_launch(void* const* d_in, const int* in_sizes, int n_in,
                              void* d_out, int out_size) {
    (void)in_sizes; (void)n_in; (void)out_size;
    const float* y        = (const float*)d_in[0];
    const float* enc_w1   = (const float*)d_in[1];
    const float* enc_b1   = (const float*)d_in[2];
    const float* enc_w2   = (const float*)d_in[3];
    const float* enc_b2   = (const float*)d_in[4];
    const float* dec_fc_w = (const float*)d_in[5];
    const float* dec_fc_b = (const float*)d_in[6];
    const float* dec_w    = (const float*)d_in[7];
    const float* dec_b    = (const float*)d_in[8];
    const float* log_pi   = (const float*)d_in[9];
    const float* log_A    = (const float*)d_in[10];
    const float* eps      = (const float*)d_in[11];
    float* out = (float*)d_out;
    float* gamma_out = out;                       // [32,128,16]
    float* xi_out    = out + BSZ * TLEN * KST;    // [32,127,16,16]

    static bool once = init_once();
    (void)once;

    prep_lplA<<<1, 32>>>(log_pi, log_A);
    transpose_w<<<dim3(13, 25), dim3(32, 8)>>>(dec_w);
    enc1_wmma<<<dim3(32, 5), 256>>>(y, enc_w1, enc_b1);
    gemm64<<<dim3(64, 1), 256>>>(p_h, H1, enc_w2, H1, enc_b2, p_ml, 32,
                                 NTOT, 32, H1, 0);
    reparam_kernel<<<(NTOT * LDIM + 255) / 256, 256>>>(eps);
    gemm64<<<dim3(64, 7), 256>>>(p_z, LDIM, dec_fc_w, 32, dec_fc_b, p_base, H1,
                                 NTOT, H1, LDIM, 0);
    dec_bce_half<<<dim3(64, 16), 256, DEC3_SMEM>>>(dec_fc_w, dec_b, y);
    fb_kernel<<<BSZ, 64>>>(gamma_out);
    xi_kernel<<<dim3(127, BSZ), 256>>>(xi_out);
}

// round 17
// speedup vs baseline: 2.9281x; 1.2519x over previous
#include <cuda_runtime.h>
#include <cuda_fp16.h>
#include <math.h>
#include <stdint.h>
#include <mma.h>

using namespace nvcuda;

// ---------------- problem constants ----------------
#define NTOT 4096      // B*T
#define TLEN 128
#define BSZ  32
#define KST  16
#define LDIM 16
#define H1   400
#define DIN  784
#define WTP  800       // g_wTh padded row length (halves)

// ---------------- scratch (device globals; no runtime alloc) ----------------
__device__ float g_h   [NTOT * H1];
__device__ float g_ml  [NTOT * 32];
__device__ float g_z   [NTOT * LDIM];
__device__ float g_base[NTOT * H1];
__device__ __half g_wTh[H1 * WTP];             // dec_w transposed + fp16
__device__ __half g_w1Th[800 * H1];            // enc_w1 transposed + fp16 (k-padded)
__device__ float g_logbk[NTOT * KST];          // [b][t][k]
__device__ float g_lA[KST * KST];
__device__ float g_lp[KST];
__device__ float g_alpha[BSZ * TLEN * KST];
__device__ float g_beta [BSZ * TLEN * KST];

// ---------------- small prep: lp, lA ----------------
__global__ void prep_lplA(const float* __restrict__ log_pi,
                          const float* __restrict__ log_A) {
    int t = threadIdx.x;
    if (t < 16) {
        float m = -1e30f;
        for (int j = 0; j < 16; j++) m = fmaxf(m, log_A[t * 16 + j]);
        float s = 0.f;
        for (int j = 0; j < 16; j++) s += expf(log_A[t * 16 + j] - m);
        for (int j = 0; j < 16; j++)
            g_lA[t * 16 + j] = logf(expf(log_A[t * 16 + j] - m) / s + 1e-9f);
    } else if (t == 16) {
        float m = -1e30f;
        for (int j = 0; j < 16; j++) m = fmaxf(m, log_pi[j]);
        float s = 0.f;
        for (int j = 0; j < 16; j++) s += expf(log_pi[j] - m);
        for (int j = 0; j < 16; j++)
            g_lp[j] = logf(expf(log_pi[j] - m) / s + 1e-9f);
    }
}

// ---------------- dec_w transpose + fp16 convert (zero-padded to WTP) -------
__global__ void transpose_w(const float* __restrict__ dec_w) {
    __shared__ float t[32][33];
    int hx = blockIdx.x * 32;   // h tile base
    int oy = blockIdx.y * 32;   // o tile base (0..800)
    int tx = threadIdx.x, ty = threadIdx.y;   // (32, 8)
    for (int r = ty; r < 32; r += 8) {
        int o = oy + r, h = hx + tx;
        t[r][tx] = (o < DIN && h < H1) ? dec_w[o * H1 + h] : 0.f;
    }
    __syncthreads();
    for (int r = ty; r < 32; r += 8) {
        int h = hx + r, o = oy + tx;
        if (h < H1 && o < WTP)
            g_wTh[h * WTP + o] = __float2half_rn(t[tx][r]);
    }
}

// ---------------- enc_w1 transpose + fp16 convert: w1[c][k] -> g_w1Th[k][c] -
__global__ void transpose_w1(const float* __restrict__ w1) {
    __shared__ float t[32][33];
    int kx = blockIdx.x * 32;   // k tile base (784)
    int cy = blockIdx.y * 32;   // c tile base (400)
    int tx = threadIdx.x, ty = threadIdx.y;   // (32, 8)
    for (int r = ty; r < 32; r += 8) {
        int c = cy + r, k = kx + tx;
        t[r][tx] = (c < H1 && k < DIN) ? w1[c * DIN + k] : 0.f;
    }
    __syncthreads();
    for (int r = ty; r < 32; r += 8) {
        int k = kx + r, c = cy + tx;
        if (k < DIN && c < H1)
            g_w1Th[k * H1 + c] = __float2half_rn(t[tx][r]);
    }
}

// ---------------- generic tiled GEMM: C = act(A @ B^T + bias) ----------------
__global__ __launch_bounds__(256) void gemm64(
    const float* __restrict__ A, int lda,
    const float* __restrict__ B, int ldb,
    const float* __restrict__ bias,
    float* __restrict__ C, int ldc,
    int M, int N, int K, int relu_flag)
{
    __shared__ float As[16][68];
    __shared__ float Bs[16][68];
    int tid = threadIdx.x;
    int tx = tid & 15, ty = tid >> 4;
    int m0 = blockIdx.x * 64, j0 = blockIdx.y * 64;
    int lr = tid >> 2;
    int lc = (tid & 3) * 4;

    float c[4][4];
    #pragma unroll
    for (int r = 0; r < 4; r++)
        #pragma unroll
        for (int s = 0; s < 4; s++) c[r][s] = 0.f;

    for (int kt = 0; kt < K; kt += 16) {
        float4 av = *(const float4*)&A[(size_t)(m0 + lr) * lda + kt + lc];
        float4 bv = make_float4(0.f, 0.f, 0.f, 0.f);
        if (j0 + lr < N)
            bv = *(const float4*)&B[(size_t)(j0 + lr) * ldb + kt + lc];
        __syncthreads();
        As[lc + 0][lr] = av.x; As[lc + 1][lr] = av.y;
        As[lc + 2][lr] = av.z; As[lc + 3][lr] = av.w;
        Bs[lc + 0][lr] = bv.x; Bs[lc + 1][lr] = bv.y;
        Bs[lc + 2][lr] = bv.z; Bs[lc + 3][lr] = bv.w;
        __syncthreads();
        #pragma unroll
        for (int kk = 0; kk < 16; kk++) {
            float4 a4 = *(const float4*)&As[kk][ty * 4];
            float4 b4 = *(const float4*)&Bs[kk][tx * 4];
            float a_[4] = {a4.x, a4.y, a4.z, a4.w};
            float b_[4] = {b4.x, b4.y, b4.z, b4.w};
            #pragma unroll
            for (int r = 0; r < 4; r++)
                #pragma unroll
                for (int s = 0; s < 4; s++)
                    c[r][s] = fmaf(a_[r], b_[s], c[r][s]);
        }
    }
    #pragma unroll
    for (int r = 0; r < 4; r++) {
        int m = m0 + ty * 4 + r;
        #pragma unroll
        for (int s = 0; s < 4; s++) {
            int j = j0 + tx * 4 + s;
            if (j < N) {
                float v = c[r][s] + bias[j];
                if (relu_flag) v = fmaxf(v, 0.f);
                C[(size_t)m * ldc + j] = v;
            }
        }
    }
}

// ---------------- reparameterization ----------------
__global__ void reparam_kernel(const float* __restrict__ eps) {
    int idx = blockIdx.x * blockDim.x + threadIdx.x;
    if (idx < NTOT * LDIM) {
        int n = idx >> 4, l = idx & 15;
        g_z[idx] = g_ml[n * 32 + l] + eps[idx] * expf(0.5f * g_ml[n * 32 + 16 + l]);
    }
}

// ---------------- MUFU-free softplus core: returns ln(1+e^{-|sv|}) ----------
__device__ __forceinline__ float softplus_tail(float sv) {
    float w = fmaxf(-fabsf(sv) * 1.4426950408889634f, -30.0f);
    float fi = floorf(w);
    float f = w - fi;
    float t = f * 0.6931471805599453f;
    float p = 1.f / 40320.f;
    p = fmaf(p, t, 1.f / 5040.f);
    p = fmaf(p, t, 1.f / 720.f);
    p = fmaf(p, t, 1.f / 120.f);
    p = fmaf(p, t, 1.f / 24.f);
    p = fmaf(p, t, 1.f / 6.f);
    p = fmaf(p, t, 0.5f);
    p = fmaf(p, t, 1.0f);
    p = fmaf(p, t, 1.0f);
    int ei = (int)fi;
    float sc = __int_as_float((unsigned)(ei + 127) << 23);
    float q = fmaf(p, sc, 1.0f);          // 1 + 2^w, in (1, 2]
    bool hi = q > 1.41421356237f;
    float qr = hi ? 0.5f * q : q;
    float z = qr - 1.0f;
    float z2 = z * z;
    float pp = 7.0376836292e-2f;
    pp = fmaf(pp, z, -1.1514610310e-1f);
    pp = fmaf(pp, z, 1.1676998740e-1f);
    pp = fmaf(pp, z, -1.2420140846e-1f);
    pp = fmaf(pp, z, 1.4249322787e-1f);
    pp = fmaf(pp, z, -1.6668057665e-1f);
    pp = fmaf(pp, z, 2.0000714765e-1f);
    pp = fmaf(pp, z, -2.4999993993e-1f);
    pp = fmaf(pp, z, 3.3333331174e-1f);
    float lnq = fmaf(z2 * z, pp, fmaf(-0.5f, z2, z));
    if (hi) lnq += 0.6931471805599453f;
    return lnq;
}
__device__ __forceinline__ float bce_term(float sv, float yy) {
    float lnq = softplus_tail(sv);
    float sp  = fminf(fmaxf(sv, 0.f) + lnq, 100.f);
    float spm = fminf(fmaxf(-sv, 0.f) + lnq, 100.f);
    return yy * spm + (1.f - yy) * sp;
}

// =============== encoder layer1 (wmma fp16, LDSM) ===========================
// grid 64: block = 64 n-rows. h = relu(y @ w1^T + b1), K=784 padded to 800.
// A = y tile fp32->fp16 in SMEM pitch 808 (1616 B, conflict-free LDSM);
// B = g_w1Th staged, pitch 264; KC=80 double-buffered; o-chunks 256+144.
#define E_APITCH 808
#define EB_PITCH 264
#define EKC      80
#define EA_BYTES (64 * E_APITCH * 2)              // 103424
#define EBBUF    (EKC * EB_PITCH * 2)             // 42240
#define E_UN     (2 * EBBUF)                      // 84480 (> Cs 66560)
#define CPITCH   260
#define E_SMEM   (EA_BYTES + E_UN + 400 * 4)      // 189504

__global__ __launch_bounds__(256, 1) void enc1_half(
    const float* __restrict__ y,
    const float* __restrict__ b1)
{
    extern __shared__ char smc[];
    __half* Ay  = (__half*)smc;                   // [64][808] halves
    char*   un  = smc + EA_BYTES;                 // B bufs / C scratch
    float*  Cs  = (float*)un;                     // [64][260]
    float*  b1s = (float*)(un + E_UN);            // [400]

    int tid = threadIdx.x, wid = tid >> 5;
    int n0 = blockIdx.x * 64;

    for (int o = tid; o < 400; o += 256) b1s[o] = b1[o];

    // zero the k-pad region (cols 784..799)
    {
        int n = tid >> 2, c = 784 + (tid & 3) * 4;
        *(uint2*)&Ay[n * E_APITCH + c] = make_uint2(0u, 0u);
    }
    // build A: Ay[n][k] = half(y[n0+n][k])
    for (int idx = tid; idx < 64 * 196; idx += 256) {
        int n = idx / 196, c = (idx % 196) * 4;
        float4 v = *(const float4*)&y[(size_t)(n0 + n) * DIN + c];
        __half2* dst = (__half2*)&Ay[n * E_APITCH + c];
        dst[0] = __floats2half2_rn(v.x, v.y);
        dst[1] = __floats2half2_rn(v.z, v.w);
    }
    __syncthreads();

    int owarp = wid * 32;

    auto stage_B = [&](int s, int o0) {
        __half* bb = (__half*)(un + (s & 1) * EBBUF);
        #pragma unroll
        for (int i = 0; i < 10; i++) {
            int u = tid + i * 256;            // 0..2559
            int row = u >> 5;
            int c8 = (u & 31) * 8;
            int o = o0 + c8;
            uint4 v = make_uint4(0u, 0u, 0u, 0u);
            if (o < H1)
                v = *(const uint4*)&g_w1Th[(size_t)(s * EKC + row) * H1 + o];
            *(uint4*)&bb[row * EB_PITCH + c8] = v;
        }
    };

    for (int oc = 0; oc < 2; oc++) {
        int o0 = oc * 256;
        int ow = (oc == 0) ? 256 : (H1 - 256);    // 256, 144
        bool wactive = owarp < ow;

        stage_B(0, o0);
        __syncthreads();

        wmma::fragment<wmma::accumulator, 16, 16, 16, float> c[4][2];
        #pragma unroll
        for (int nt = 0; nt < 4; nt++)
            #pragma unroll
            for (int hf = 0; hf < 2; hf++) wmma::fill_fragment(c[nt][hf], 0.f);

        for (int st = 0; st < 10; st++) {
            if (st < 9) stage_B(st + 1, o0);
            if (wactive) {
                const __half* Bst = (const __half*)(un + (st & 1) * EBBUF);
                #pragma unroll
                for (int ksl = 0; ksl < 5; ksl++) {
                    int kk = st * EKC + ksl * 16;
                    wmma::fragment<wmma::matrix_a, 16, 16, 16, __half,
                                   wmma::row_major> a[4];
                    wmma::fragment<wmma::matrix_b, 16, 16, 16, __half,
                                   wmma::row_major> b0, b1f;
                    #pragma unroll
                    for (int nt = 0; nt < 4; nt++)
                        wmma::load_matrix_sync(a[nt], Ay + nt * 16 * E_APITCH + kk,
                                               E_APITCH);
                    wmma::load_matrix_sync(b0, Bst + (ksl * 16) * EB_PITCH + owarp,
                                           EB_PITCH);
                    wmma::load_matrix_sync(b1f, Bst + (ksl * 16) * EB_PITCH + owarp + 16,
                                           EB_PITCH);
                    #pragma unroll
                    for (int nt = 0; nt < 4; nt++) {
                        wmma::mma_sync(c[nt][0], a[nt], b0, c[nt][0]);
                        wmma::mma_sync(c[nt][1], a[nt], b1f, c[nt][1]);
                    }
                }
            }
            __syncthreads();
        }

        if (wactive) {
            #pragma unroll
            for (int nt = 0; nt < 4; nt++)
                #pragma unroll
                for (int hf = 0; hf < 2; hf++)
                    wmma::store_matrix_sync(Cs + nt * 16 * CPITCH + owarp + hf * 16,
                                            c[nt][hf], CPITCH, wmma::mem_row_major);
        }
        __syncthreads();

        // epilogue: h = relu(C + b1)
        {
            int n = tid >> 2;
            int ob = (tid & 3) * 64;
            const float* crow = &Cs[n * CPITCH];
            for (int j = 0; j < 64; j += 4) {
                int o = ob + j;
                if (o >= ow) break;
                float4 cv = *(const float4*)&crow[o];
                float4 db = *(const float4*)&b1s[o0 + o];
                float4 r;
                r.x = fmaxf(cv.x + db.x, 0.f);
                r.y = fmaxf(cv.y + db.y, 0.f);
                r.z = fmaxf(cv.z + db.z, 0.f);
                r.w = fmaxf(cv.w + db.w, 0.f);
                *(float4*)&g_h[(size_t)(n0 + n) * H1 + o0 + o] = r;
            }
        }
        __syncthreads();
    }
}

// =============== fused decoder GEMM (wmma fp16, LDSM) + BCE =================
#define APITCH_H 408
#define BPITCH_H 264
#define KC       80
#define HK_BYTES (64 * APITCH_H * 2)                  // 52224
#define BBUF_BYTES (KC * BPITCH_H * 2)                // 42240 per buffer
#define UN_BYTES (2 * BBUF_BYTES)                     // 84480 (> Cs 66560)
#define DEC3_SMEM (HK_BYTES + UN_BYTES + 784 * 4 + 400 * 4)   // 141,440

__global__ __launch_bounds__(256, 1) void dec_bce_half(
    const float* __restrict__ dec_fc_w,
    const float* __restrict__ dec_b,
    const float* __restrict__ y)
{
    extern __shared__ char smc[];
    __half* hk  = (__half*)smc;                       // [64][408] halves
    char*   un  = smc + HK_BYTES;                     // B bufs / C scratch
    float*  Cs  = (float*)un;                         // [64][260]
    float* decb = (float*)(un + UN_BYTES);            // [784]
    float* wxk  = decb + 784;                         // [400]

    int tid = threadIdx.x, wid = tid >> 5;
    int k  = blockIdx.y;
    int n0 = blockIdx.x * 64;

    for (int h = tid; h < 400; h += 256) wxk[h] = dec_fc_w[h * 32 + 16 + k];
    for (int o = tid; o < 784; o += 256) decb[o] = dec_b[o];
    __syncthreads();

    #pragma unroll 5
    for (int idx = tid; idx < 6400; idx += 256) {
        int n = idx / 100, c = (idx % 100) * 4;
        float4 v = *(const float4*)&g_base[(size_t)(n0 + n) * 400 + c];
        __half2* dst = (__half2*)&hk[n * APITCH_H + c];
        dst[0] = __floats2half2_rn(fmaxf(v.x + wxk[c + 0], 0.f),
                                   fmaxf(v.y + wxk[c + 1], 0.f));
        dst[1] = __floats2half2_rn(fmaxf(v.z + wxk[c + 2], 0.f),
                                   fmaxf(v.w + wxk[c + 3], 0.f));
    }
    __syncthreads();

    float acc = 0.f;
    int owarp = wid * 32;

    auto stage_B = [&](int s, int o0) {
        __half* bb = (__half*)(un + (s & 1) * BBUF_BYTES);
        #pragma unroll
        for (int i = 0; i < 10; i++) {
            int u = tid + i * 256;
            int row = u >> 5;
            int c8 = (u & 31) * 8;
            int o = o0 + c8;
            uint4 v = make_uint4(0u, 0u, 0u, 0u);
            if (o < DIN)
                v = *(const uint4*)&g_wTh[(size_t)(s * KC + row) * WTP + o];
            *(uint4*)&bb[row * BPITCH_H + c8] = v;
        }
    };

    for (int oc = 0; oc < 4; oc++) {
        int o0 = oc * 256;
        int ow = (o0 + 256 <= DIN) ? 256 : (DIN - o0);   // 256,256,256,16
        bool wactive = owarp < ow;

        stage_B(0, o0);
        __syncthreads();

        wmma::fragment<wmma::accumulator, 16, 16, 16, float> c[4][2];
        #pragma unroll
        for (int nt = 0; nt < 4; nt++)
            #pragma unroll
            for (int hf = 0; hf < 2; hf++) wmma::fill_fragment(c[nt][hf], 0.f);

        for (int st = 0; st < 5; st++) {
            if (st < 4) stage_B(st + 1, o0);
            if (wactive) {
                const __half* Bst = (const __half*)(un + (st & 1) * BBUF_BYTES);
                #pragma unroll
                for (int ksl = 0; ksl < 5; ksl++) {
                    int kk = st * KC + ksl * 16;
                    wmma::fragment<wmma::matrix_a, 16, 16, 16, __half,
                                   wmma::row_major> a[4];
                    wmma::fragment<wmma::matrix_b, 16, 16, 16, __half,
                                   wmma::row_major> b0, b1;
                    #pragma unroll
                    for (int nt = 0; nt < 4; nt++)
                        wmma::load_matrix_sync(a[nt], hk + nt * 16 * APITCH_H + kk,
                                               APITCH_H);
                    wmma::load_matrix_sync(b0, Bst + (ksl * 16) * BPITCH_H + owarp,
                                           BPITCH_H);
                    wmma::load_matrix_sync(b1, Bst + (ksl * 16) * BPITCH_H + owarp + 16,
                                           BPITCH_H);
                    #pragma unroll
                    for (int nt = 0; nt < 4; nt++) {
                        wmma::mma_sync(c[nt][0], a[nt], b0, c[nt][0]);
                        wmma::mma_sync(c[nt][1], a[nt], b1, c[nt][1]);
                    }
                }
            }
            __syncthreads();
        }

        if (wactive) {
            #pragma unroll
            for (int nt = 0; nt < 4; nt++)
                #pragma unroll
                for (int hf = 0; hf < 2; hf++)
                    wmma::store_matrix_sync(Cs + nt * 16 * CPITCH + owarp + hf * 16,
                                            c[nt][hf], CPITCH, wmma::mem_row_major);
        }
        __syncthreads();

        {
            int n = tid >> 2;
            int ob = (tid & 3) * 64;
            const float* yrow = y + (size_t)(n0 + n) * DIN + o0;
            const float* crow = &Cs[n * CPITCH];
            for (int j = 0; j < 64; j += 4) {
                int o = ob + j;
                if (o >= ow) break;
                float4 cv = *(const float4*)&crow[o];
                float4 yv = *(const float4*)&yrow[o];
                float4 db = *(const float4*)&decb[o0 + o];
                acc += bce_term(cv.x + db.x, yv.x);
                acc += bce_term(cv.y + db.y, yv.y);
                acc += bce_term(cv.z + db.z, yv.z);
                acc += bce_term(cv.w + db.w, yv.w);
            }
        }
        __syncthreads();
    }

    acc += __shfl_xor_sync(0xffffffffu, acc, 1, 4);
    acc += __shfl_xor_sync(0xffffffffu, acc, 2, 4);
    if ((tid & 3) == 0)
        g_logbk[(size_t)(n0 + (tid >> 2)) * KST + k] = -acc * 0.01f;
}

// ---------------- HMM forward/backward + gamma ----------------
__global__ void fb_kernel(float* __restrict__ gamma_out) {
    int b = blockIdx.x;
    int tid = threadIdx.x;
    int lane = tid & 31, wid = tid >> 5;
    __shared__ float lAs[256];
    for (int i = tid; i < 256; i += 64) lAs[i] = g_lA[i];
    __syncthreads();
    const float* lb = g_logbk + (size_t)b * TLEN * KST;

    if (wid == 0 && lane < 16) {            // forward
        int j = lane;
        float lacol[16];
        #pragma unroll
        for (int i = 0; i < 16; i++) lacol[i] = lAs[i * 16 + j];
        float prev = g_lp[j] + lb[j];
        g_alpha[((size_t)b * 128 + 0) * 16 + j] = prev;
        for (int t = 1; t < 128; t++) {
            float v[16]; float m = -1e30f;
            #pragma unroll
            for (int i = 0; i < 16; i++) {
                v[i] = __shfl_sync(0xffffu, prev, i, 16) + lacol[i];
                m = fmaxf(m, v[i]);
            }
            float s = 0.f;
            #pragma unroll
            for (int i = 0; i < 16; i++) s += expf(v[i] - m);
            prev = m + logf(s) + lb[t * 16 + j];
            g_alpha[((size_t)b * 128 + t) * 16 + j] = prev;
        }
    } else if (wid == 1 && lane < 16) {     // backward
        int i = lane;
        float larow[16];
        #pragma unroll
        for (int j = 0; j < 16; j++) larow[j] = lAs[i * 16 + j];
        float bprev = 0.f;
        g_beta[((size_t)b * 128 + 127) * 16 + i] = 0.f;
        for (int t = 126; t >= 0; t--) {
            float w = bprev + lb[(t + 1) * 16 + i];
            float v[16]; float m = -1e30f;
            #pragma unroll
            for (int j = 0; j < 16; j++) {
                v[j] = __shfl_sync(0xffffu, w, j, 16) + larow[j];
                m = fmaxf(m, v[j]);
            }
            float s = 0.f;
            #pragma unroll
            for (int j = 0; j < 16; j++) s += expf(v[j] - m);
            bprev = m + logf(s);
            g_beta[((size_t)b * 128 + t) * 16 + i] = bprev;
        }
    }
    __syncthreads();

    int kk = tid & 15;
    for (int t = tid >> 4; t < 128; t += 4) {
        size_t off = ((size_t)b * 128 + t) * 16 + kk;
        float lg = g_alpha[off] + g_beta[off];
        float m = lg;
        m = fmaxf(m, __shfl_xor_sync(0xffffffffu, m, 8, 16));
        m = fmaxf(m, __shfl_xor_sync(0xffffffffu, m, 4, 16));
        m = fmaxf(m, __shfl_xor_sync(0xffffffffu, m, 2, 16));
        m = fmaxf(m, __shfl_xor_sync(0xffffffffu, m, 1, 16));
        float e = expf(lg - m);
        float s = e;
        s += __shfl_xor_sync(0xffffffffu, s, 8, 16);
        s += __shfl_xor_sync(0xffffffffu, s, 4, 16);
        s += __shfl_xor_sync(0xffffffffu, s, 2, 16);
        s += __shfl_xor_sync(0xffffffffu, s, 1, 16);
        gamma_out[off] = e / s;
    }
}

// ---------------- xi ----------------
__global__ void xi_kernel(float* __restrict__ xi_out) {
    int t = blockIdx.x;    // 0..126
    int b = blockIdx.y;
    int tid = threadIdx.x; // 256
    int i = tid >> 4, j = tid & 15;
    int lane = tid & 31, wid = tid >> 5;

    float v = g_alpha[((size_t)b * 128 + t) * 16 + i] + g_lA[i * 16 + j]
            + g_logbk[((size_t)b * 128 + t + 1) * 16 + j]
            + g_beta [((size_t)b * 128 + t + 1) * 16 + j];

    __shared__ float rbuf[8];
    float m = v;
    #pragma unroll
    for (int off = 16; off >= 1; off >>= 1)
        m = fmaxf(m, __shfl_xor_sync(0xffffffffu, m, off));
    if (lane == 0) rbuf[wid] = m;
    __syncthreads();
    float bm = rbuf[0];
    #pragma unroll
    for (int w = 1; w < 8; w++) bm = fmaxf(bm, rbuf[w]);
    __syncthreads();

    float e = expf(v - bm);
    float s = e;
    #pragma unroll
    for (int off = 16; off >= 1; off >>= 1)
        s += __shfl_xor_sync(0xffffffffu, s, off);
    if (lane == 0) rbuf[wid] = s;
    __syncthreads();
    float bs = 0.f;
    #pragma unroll
    for (int w = 0; w < 8; w++) bs += rbuf[w];

    xi_out[(((size_t)b * 127 + t) * 256) + tid] = e / bs;
}

// ---------------- host launcher ----------------
static float *p_h = nullptr, *p_ml = nullptr, *p_z = nullptr, *p_base = nullptr;

static bool init_once() {
    cudaGetSymbolAddress((void**)&p_h, g_h);
    cudaGetSymbolAddress((void**)&p_ml, g_ml);
    cudaGetSymbolAddress((void**)&p_z, g_z);
    cudaGetSymbolAddress((void**)&p_base, g_base);
    cudaFuncSetAttribute(dec_bce_half, cudaFuncAttributeMaxDynamicSharedMemorySize,
                         DEC3_SMEM);
    cudaFuncSetAttribute(enc1_half, cudaFuncAttributeMaxDynamicSharedMemorySize,
                         E_SMEM);
    return true;
}

extern "C" void kernel_launch(void* const* d_in, const int* in_sizes, int n_in,
                              void* d_out, int out_size) {
    (void)in_sizes; (void)n_in; (void)out_size;
    const float* y        = (const float*)d_in[0];
    const float* enc_w1   = (const float*)d_in[1];
    const float* enc_b1   = (const float*)d_in[2];
    const float* enc_w2   = (const float*)d_in[3];
    const float* enc_b2   = (const float*)d_in[4];
    const float* dec_fc_w = (const float*)d_in[5];
    const float* dec_fc_b = (const float*)d_in[6];
    const float* dec_w    = (const float*)d_in[7];
    const float* dec_b    = (const float*)d_in[8];
    const float* log_pi   = (const float*)d_in[9];
    const float* log_A    = (const float*)d_in[10];
    const float* eps      = (const float*)d_in[11];
    float* out = (float*)d_out;
    float* gamma_out = out;                       // [32,128,16]
    float* xi_out    = out + BSZ * TLEN * KST;    // [32,127,16,16]

    static bool once = init_once();
    (void)once;

    prep_lplA<<<1, 32>>>(log_pi, log_A);
    transpose_w<<<dim3(13, 25), dim3(32, 8)>>>(dec_w);
    transpose_w1<<<dim3(25, 13), dim3(32, 8)>>>(enc_w1);
    enc1_half<<<64, 256, E_SMEM>>>(y, enc_b1);
    gemm64<<<dim3(64, 1), 256>>>(p_h, H1, enc_w2, H1, enc_b2, p_ml, 32,
                                 NTOT, 32, H1, 0);
    reparam_kernel<<<(NTOT * LDIM + 255) / 256, 256>>>(eps);
    gemm64<<<dim3(64, 7), 256>>>(p_z, LDIM, dec_fc_w, 32, dec_fc_b, p_base, H1,
                                 NTOT, H1, LDIM, 0);
    dec_bce_half<<<dim3(64, 16), 256, DEC3_SMEM>>>(dec_fc_w, dec_b, y);
    fb_kernel<<<BSZ, 64>>>(gamma_out);
    xi_kernel<<<dim3(127, BSZ), 256>>>(xi_out);
}